// round 2
// baseline (speedup 1.0000x reference)
#include <cuda_runtime.h>
#include <cuda_bf16.h>
#include <math.h>

// ---------------- problem constants (fixed by reference setup) ----------------
#define BB     2
#define S_IMG  2048
#define S_TXT  256
#define S_TOT  2304          // S_IMG + S_TXT
#define NH     24
#define DHD    128
#define DD     3072          // NH * DHD
#define ATT_SCALE 0.08838834764831845f   // DH^-0.5
#define RMS_EPS   1e-5f

#define M_IMG  (BB * S_IMG)  // 4096
#define M_TXT  (BB * S_TXT)  // 512
#define IMG_OUT_ELEMS (M_IMG * DD)   // 12582912

// ---------------- device scratch (allocation-free rule: __device__ globals) ---
__device__ float g_Q[BB * NH * S_TOT * DHD];   // [B,H,S,DH]
__device__ float g_K[BB * NH * S_TOT * DHD];
__device__ float g_V[BB * NH * S_TOT * DHD];
__device__ float g_O[BB * S_TOT * DD];         // [B,S,D]

// =============================================================================
// SGEMM: C[M,N] = A[M,K] @ W[K,N] + bias[N]
//   128x128 block tile, BK=16, 256 threads, 8x8 per thread.
//   a_gather: A row r -> (r/a_seg)*S_TOT + a_base + r%a_seg   (gather from g_O)
//   out_scatter: write into [B,H,S,DH] layout with s_offset (QKV path)
// All dims are multiples of tile sizes for this problem -> no bounds checks.
// =============================================================================
__global__ void __launch_bounds__(256) sgemm_kernel(
    const float* __restrict__ A, const float* __restrict__ W,
    const float* __restrict__ bias, float* __restrict__ out,
    int M, int N, int K,
    int a_gather, int a_seg, int a_base,
    int out_scatter, int s_offset, int o_seg)
{
    __shared__ float As[16][128];
    __shared__ float Bs[16][128];

    const int tid = threadIdx.x;
    const int tx = tid & 15, ty = tid >> 4;
    const int bm = blockIdx.y << 7, bn = blockIdx.x << 7;

    float acc[8][8];
#pragma unroll
    for (int i = 0; i < 8; i++)
#pragma unroll
        for (int j = 0; j < 8; j++) acc[i][j] = 0.f;

    // Hoist A row gather (independent of k0)
    int r0 = (tid + 0) >> 2, r1 = (tid + 256) >> 2;
    int q0 = ((tid + 0) & 3) << 2, q1 = ((tid + 256) & 3) << 2;
    int gr0 = bm + r0, gr1 = bm + r1;
    int ar0 = a_gather ? ((gr0 / a_seg) * S_TOT + a_base + (gr0 % a_seg)) : gr0;
    int ar1 = a_gather ? ((gr1 / a_seg) * S_TOT + a_base + (gr1 % a_seg)) : gr1;
    const float* Arow0 = A + (size_t)ar0 * K;
    const float* Arow1 = A + (size_t)ar1 * K;

    int kr0 = (tid + 0) >> 5, nq0 = ((tid + 0) & 31) << 2;
    int kr1 = (tid + 256) >> 5, nq1 = ((tid + 256) & 31) << 2;

    for (int k0 = 0; k0 < K; k0 += 16) {
        float4 va0 = *(const float4*)(Arow0 + k0 + q0);
        float4 va1 = *(const float4*)(Arow1 + k0 + q1);
        As[q0 + 0][r0] = va0.x; As[q0 + 1][r0] = va0.y;
        As[q0 + 2][r0] = va0.z; As[q0 + 3][r0] = va0.w;
        As[q1 + 0][r1] = va1.x; As[q1 + 1][r1] = va1.y;
        As[q1 + 2][r1] = va1.z; As[q1 + 3][r1] = va1.w;
        *(float4*)(&Bs[kr0][nq0]) = *(const float4*)(W + (size_t)(k0 + kr0) * N + bn + nq0);
        *(float4*)(&Bs[kr1][nq1]) = *(const float4*)(W + (size_t)(k0 + kr1) * N + bn + nq1);
        __syncthreads();

#pragma unroll
        for (int kk = 0; kk < 16; kk++) {
            float4 a0 = *(const float4*)(&As[kk][ty * 8]);
            float4 a1 = *(const float4*)(&As[kk][ty * 8 + 4]);
            float4 b0 = *(const float4*)(&Bs[kk][tx * 8]);
            float4 b1 = *(const float4*)(&Bs[kk][tx * 8 + 4]);
            float a[8] = {a0.x, a0.y, a0.z, a0.w, a1.x, a1.y, a1.z, a1.w};
            float b[8] = {b0.x, b0.y, b0.z, b0.w, b1.x, b1.y, b1.z, b1.w};
#pragma unroll
            for (int i = 0; i < 8; i++)
#pragma unroll
                for (int j = 0; j < 8; j++) acc[i][j] += a[i] * b[j];
        }
        __syncthreads();
    }

#pragma unroll
    for (int i = 0; i < 8; i++) {
        int r = bm + ty * 8 + i;
        int ob = 0, sl = 0;
        if (out_scatter) { ob = r / o_seg; sl = r % o_seg; }
#pragma unroll
        for (int j = 0; j < 8; j++) {
            int n = bn + tx * 8 + j;
            float c = acc[i][j] + bias[n];
            if (out_scatter) {
                int h = n >> 7, dd = n & 127;
                out[(((size_t)(ob * NH + h)) * S_TOT + (s_offset + sl)) * DHD + dd] = c;
            } else {
                out[(size_t)r * N + n] = c;
            }
        }
    }
}

// =============================================================================
// Fused RMSNorm (+g) + RoPE, in place on [B,H,S,DH] buffer.
// One block (128 threads) per (b,h,s) row.
// =============================================================================
__global__ void __launch_bounds__(128) norm_rope_kernel(
    float* __restrict__ X,
    const float* __restrict__ g_main, const float* __restrict__ g_add,
    const float* __restrict__ cosI, const float* __restrict__ sinI,
    const float* __restrict__ cosT, const float* __restrict__ sinT)
{
    const int row = blockIdx.x;            // bh * S_TOT + s
    const int s = row % S_TOT;
    const int d = threadIdx.x;             // 0..127
    float x = X[(size_t)row * DHD + d];

    // block reduce of x^2 over 128 threads (4 warps)
    float v = x * x;
#pragma unroll
    for (int off = 16; off > 0; off >>= 1)
        v += __shfl_xor_sync(0xffffffffu, v, off);
    __shared__ float ws[4];
    int lane = d & 31, wid = d >> 5;
    if (lane == 0) ws[wid] = v;
    __syncthreads();
    float tot = ws[0] + ws[1] + ws[2] + ws[3];
    float rn = rsqrtf(tot * (1.f / DHD) + RMS_EPS);

    bool img = (s < S_IMG);
    float g = img ? g_main[d] : g_add[d];
    float xn = x * rn * g;

    int fi = d >> 1;
    int fs = img ? s : (s - S_IMG);
    const float* cp = img ? cosI : cosT;
    const float* sp = img ? sinI : sinT;
    float c = cp[fs * (DHD / 2) + fi];
    float sv = sp[fs * (DHD / 2) + fi];

    float other = __shfl_xor_sync(0xffffffffu, xn, 1);
    float outv = ((d & 1) == 0) ? (xn * c - other * sv)   // o0 = x0*c - x1*s
                                : (other * sv + xn * c);  // o1 = x0*s + x1*c
    X[(size_t)row * DHD + d] = outv;
}

// =============================================================================
// Flash attention, fp32, online softmax.
// grid = (S_TOT/64, B*H), 256 threads (tx=tid&15, ty=tid>>4).
// Thread (ty,tx): q rows {ty+16i}, key cols {tx+16j}  -> smem accesses are
// broadcast or conflict-free.  Writes O as [B,S,D].
// =============================================================================
#define ATT_SMEM_FLOATS (64*132 + 64*132 + 64*128 + 64*68)

__global__ void __launch_bounds__(256) attn_kernel(
    const float* __restrict__ Q, const float* __restrict__ K,
    const float* __restrict__ V, const int* __restrict__ mask,
    float* __restrict__ O)
{
    extern __shared__ float sm[];
    float* Qs = sm;                      // [64][132]
    float* Ks = Qs + 64 * 132;           // [64][132]
    float* Vs = Ks + 64 * 132;           // [64][128]
    float* Ps = Vs + 64 * 128;           // [64][68]

    const int tid = threadIdx.x;
    const int tx = tid & 15, ty = tid >> 4;
    const int qt = blockIdx.x;
    const int bh = blockIdx.y;
    const int b = bh / NH, h = bh % NH;
    const int q0 = qt * 64;

    const float* Qb = Q + (size_t)bh * S_TOT * DHD + (size_t)q0 * DHD;
    const float* Kb = K + (size_t)bh * S_TOT * DHD;
    const float* Vb = V + (size_t)bh * S_TOT * DHD;

    // load Q tile (coalesced float4 loads, conflict-free float4 smem stores)
    for (int idx = tid; idx < 64 * 32; idx += 256) {
        int r = idx >> 5, c4 = (idx & 31) << 2;
        *(float4*)(Qs + r * 132 + c4) = *(const float4*)(Qb + r * DHD + c4);
    }
    __syncthreads();

    float m[4], l[4], o[4][8];
#pragma unroll
    for (int i = 0; i < 4; i++) {
        m[i] = -1e30f; l[i] = 0.f;
#pragma unroll
        for (int c = 0; c < 8; c++) o[i][c] = 0.f;
    }

    for (int kt = 0; kt < S_TOT / 64; kt++) {
        const int k0 = kt * 64;
        for (int idx = tid; idx < 64 * 32; idx += 256) {
            int r = idx >> 5, c4 = (idx & 31) << 2;
            *(float4*)(Ks + r * 132 + c4) = *(const float4*)(Kb + (size_t)(k0 + r) * DHD + c4);
            *(float4*)(Vs + r * 128 + c4) = *(const float4*)(Vb + (size_t)(k0 + r) * DHD + c4);
        }
        __syncthreads();

        // scores S[4][4]
        float s[4][4];
#pragma unroll
        for (int i = 0; i < 4; i++)
#pragma unroll
            for (int j = 0; j < 4; j++) s[i][j] = 0.f;

        for (int d = 0; d < DHD; d += 4) {
            float4 a[4], bq[4];
#pragma unroll
            for (int i = 0; i < 4; i++) a[i] = *(const float4*)(Qs + (ty + 16 * i) * 132 + d);
#pragma unroll
            for (int j = 0; j < 4; j++) bq[j] = *(const float4*)(Ks + (tx + 16 * j) * 132 + d);
#pragma unroll
            for (int i = 0; i < 4; i++)
#pragma unroll
                for (int j = 0; j < 4; j++)
                    s[i][j] += a[i].x * bq[j].x + a[i].y * bq[j].y +
                               a[i].z * bq[j].z + a[i].w * bq[j].w;
        }

        // scale + mask bias (matches reference: score*SCALE + (-1e9) on masked)
#pragma unroll
        for (int j = 0; j < 4; j++) {
            int kg = k0 + tx + 16 * j;
            float biasv = 0.f;
            if (kg >= S_IMG && mask[b * S_TXT + (kg - S_IMG)] == 0) biasv = -1e9f;
#pragma unroll
            for (int i = 0; i < 4; i++) s[i][j] = s[i][j] * ATT_SCALE + biasv;
        }

        // online softmax update (16 lanes sharing a q row compute identically)
#pragma unroll
        for (int i = 0; i < 4; i++) {
            float mt = fmaxf(fmaxf(s[i][0], s[i][1]), fmaxf(s[i][2], s[i][3]));
            mt = fmaxf(mt, __shfl_xor_sync(0xffffffffu, mt, 8));
            mt = fmaxf(mt, __shfl_xor_sync(0xffffffffu, mt, 4));
            mt = fmaxf(mt, __shfl_xor_sync(0xffffffffu, mt, 2));
            mt = fmaxf(mt, __shfl_xor_sync(0xffffffffu, mt, 1));
            float mn = fmaxf(m[i], mt);
            float al = __expf(m[i] - mn);
            float rs = 0.f;
#pragma unroll
            for (int j = 0; j < 4; j++) {
                float p = __expf(s[i][j] - mn);
                Ps[(ty + 16 * i) * 68 + tx + 16 * j] = p;
                rs += p;
            }
            rs += __shfl_xor_sync(0xffffffffu, rs, 8);
            rs += __shfl_xor_sync(0xffffffffu, rs, 4);
            rs += __shfl_xor_sync(0xffffffffu, rs, 2);
            rs += __shfl_xor_sync(0xffffffffu, rs, 1);
            l[i] = l[i] * al + rs;
            m[i] = mn;
#pragma unroll
            for (int c = 0; c < 8; c++) o[i][c] *= al;
        }
        __syncthreads();

        // O += P @ V   (cols tx*4..+3 and 64+tx*4..+3)
        for (int k = 0; k < 64; k++) {
            float4 v0 = *(const float4*)(Vs + k * 128 + 4 * tx);
            float4 v1 = *(const float4*)(Vs + k * 128 + 64 + 4 * tx);
#pragma unroll
            for (int i = 0; i < 4; i++) {
                float a = Ps[(ty + 16 * i) * 68 + k];
                o[i][0] += a * v0.x; o[i][1] += a * v0.y;
                o[i][2] += a * v0.z; o[i][3] += a * v0.w;
                o[i][4] += a * v1.x; o[i][5] += a * v1.y;
                o[i][6] += a * v1.z; o[i][7] += a * v1.w;
            }
        }
        __syncthreads();
    }

    // write out: O[b][s][h*128 + col]
#pragma unroll
    for (int i = 0; i < 4; i++) {
        float inv = 1.f / l[i];
        int sg = q0 + ty + 16 * i;
        float* op = O + ((size_t)(b * S_TOT + sg)) * DD + h * DHD;
        float4 r0 = make_float4(o[i][0] * inv, o[i][1] * inv, o[i][2] * inv, o[i][3] * inv);
        float4 r1 = make_float4(o[i][4] * inv, o[i][5] * inv, o[i][6] * inv, o[i][7] * inv);
        *(float4*)(op + 4 * tx) = r0;
        *(float4*)(op + 64 + 4 * tx) = r1;
    }
}

// =============================================================================
// Launch
// =============================================================================
extern "C" void kernel_launch(void* const* d_in, const int* in_sizes, int n_in,
                              void* d_out, int out_size)
{
    const float* hidden = (const float*)d_in[0];
    const float* enc    = (const float*)d_in[1];
    const int*   mask   = (const int*)d_in[2];
    // txt_seq_lens may be at index 3 (dict order) or 7 (signature order)
    const int fb = (in_sizes[3] == 2) ? 4 : 3;
    const float* cosI = (const float*)d_in[fb + 0];
    const float* sinI = (const float*)d_in[fb + 1];
    const float* cosT = (const float*)d_in[fb + 2];
    const float* sinT = (const float*)d_in[fb + 3];
    const float* wq     = (const float*)d_in[8];
    const float* bq     = (const float*)d_in[9];
    const float* wk     = (const float*)d_in[10];
    const float* bk     = (const float*)d_in[11];
    const float* wv     = (const float*)d_in[12];
    const float* bv     = (const float*)d_in[13];
    const float* wq_add = (const float*)d_in[14];
    const float* bq_add = (const float*)d_in[15];
    const float* wk_add = (const float*)d_in[16];
    const float* bk_add = (const float*)d_in[17];
    const float* wv_add = (const float*)d_in[18];
    const float* bv_add = (const float*)d_in[19];
    const float* wo     = (const float*)d_in[20];
    const float* bo     = (const float*)d_in[21];
    const float* wo_add = (const float*)d_in[22];
    const float* bo_add = (const float*)d_in[23];
    const float* gq     = (const float*)d_in[24];
    const float* gk     = (const float*)d_in[25];
    const float* gq_add = (const float*)d_in[26];
    const float* gk_add = (const float*)d_in[27];

    float* out = (float*)d_out;

    float *Qp, *Kp, *Vp, *Op;
    cudaGetSymbolAddress((void**)&Qp, g_Q);
    cudaGetSymbolAddress((void**)&Kp, g_K);
    cudaGetSymbolAddress((void**)&Vp, g_V);
    cudaGetSymbolAddress((void**)&Op, g_O);

    const size_t attn_smem = ATT_SMEM_FLOATS * sizeof(float);
    cudaFuncSetAttribute(attn_kernel, cudaFuncAttributeMaxDynamicSharedMemorySize,
                         (int)attn_smem);

    dim3 blk(256);
    dim3 grid_img(DD / 128, M_IMG / 128);   // (24, 32)
    dim3 grid_txt(DD / 128, M_TXT / 128);   // (24, 4)

    // QKV projections (scatter into [B,H,S,DH])
    sgemm_kernel<<<grid_img, blk>>>(hidden, wq, bq, Qp, M_IMG, DD, DD, 0, 1, 0, 1, 0, S_IMG);
    sgemm_kernel<<<grid_img, blk>>>(hidden, wk, bk, Kp, M_IMG, DD, DD, 0, 1, 0, 1, 0, S_IMG);
    sgemm_kernel<<<grid_img, blk>>>(hidden, wv, bv, Vp, M_IMG, DD, DD, 0, 1, 0, 1, 0, S_IMG);
    sgemm_kernel<<<grid_txt, blk>>>(enc, wq_add, bq_add, Qp, M_TXT, DD, DD, 0, 1, 0, 1, S_IMG, S_TXT);
    sgemm_kernel<<<grid_txt, blk>>>(enc, wk_add, bk_add, Kp, M_TXT, DD, DD, 0, 1, 0, 1, S_IMG, S_TXT);
    sgemm_kernel<<<grid_txt, blk>>>(enc, wv_add, bv_add, Vp, M_TXT, DD, DD, 0, 1, 0, 1, S_IMG, S_TXT);

    // RMSNorm + RoPE on Q and K
    int nrows = BB * NH * S_TOT;
    norm_rope_kernel<<<nrows, 128>>>(Qp, gq, gq_add, cosI, sinI, cosT, sinT);
    norm_rope_kernel<<<nrows, 128>>>(Kp, gk, gk_add, cosI, sinI, cosT, sinT);

    // Attention -> g_O [B,S,D]
    attn_kernel<<<dim3(S_TOT / 64, BB * NH), blk, attn_smem>>>(Qp, Kp, Vp, mask, Op);

    // Output projections (gather from g_O)
    sgemm_kernel<<<grid_img, blk>>>(Op, wo, bo, out, M_IMG, DD, DD,
                                    1, S_IMG, 0, 0, 0, S_IMG);
    sgemm_kernel<<<grid_txt, blk>>>(Op, wo_add, bo_add, out + IMG_OUT_ELEMS, M_TXT, DD, DD,
                                    1, S_TXT, S_IMG, 0, 0, S_TXT);
}

// round 6
// speedup vs baseline: 1.7255x; 1.7255x over previous
#include <cuda_runtime.h>
#include <cuda_bf16.h>
#include <math.h>
#include <stdint.h>

// ---------------- problem constants ----------------
#define BB     2
#define S_IMG  2048
#define S_TXT  256
#define S_TOT  2304
#define NH     24
#define DHD    128
#define DD     3072
#define ATT_SCALE 0.08838834764831845f
#define RMS_EPS   1e-5f

#define M_IMG  (BB * S_IMG)          // 4096
#define M_TXT  (BB * S_TXT)          // 512
#define M_O    (BB * S_TOT)          // 4608
#define IMG_OUT_ELEMS (M_IMG * DD)

// ---------------- device scratch ----------------
__device__ float g_Q[BB * NH * S_TOT * DHD];
__device__ float g_K[BB * NH * S_TOT * DHD];
__device__ float g_V[BB * NH * S_TOT * DHD];
__device__ float g_O[M_O * DD];

__device__ __nv_bfloat16 g_Whi[8][DD * DD];   // transposed [N,K] bf16 hi
__device__ __nv_bfloat16 g_Wlo[8][DD * DD];   // transposed [N,K] bf16 lo
__device__ __nv_bfloat16 g_Hhi[M_IMG * DD], g_Hlo[M_IMG * DD];
__device__ __nv_bfloat16 g_Ehi[M_TXT * DD], g_Elo[M_TXT * DD];
__device__ __nv_bfloat16 g_Shi[M_O * DD],  g_Slo[M_O * DD];

// ---------------- PTX helpers (sm_80+ only: mma.sync / ldmatrix / cp.async) --
__device__ __forceinline__ uint32_t smem_u32(const void* p) {
    uint32_t a;
    asm("{ .reg .u64 t; cvta.to.shared.u64 t, %1; cvt.u32.u64 %0, t; }" : "=r"(a) : "l"(p));
    return a;
}
#define CP_ASYNC16(sa, gp) \
    asm volatile("cp.async.cg.shared.global [%0], [%1], 16;" :: "r"(sa), "l"(gp) : "memory")
#define CP_COMMIT() asm volatile("cp.async.commit_group;" ::: "memory")
#define CP_WAIT(n)  asm volatile("cp.async.wait_group %0;" :: "n"(n) : "memory")

__device__ __forceinline__ void ldsm_x4(uint32_t& r0, uint32_t& r1, uint32_t& r2,
                                        uint32_t& r3, uint32_t addr) {
    asm volatile("ldmatrix.sync.aligned.m8n8.x4.shared.b16 {%0,%1,%2,%3}, [%4];"
                 : "=r"(r0), "=r"(r1), "=r"(r2), "=r"(r3) : "r"(addr));
}
__device__ __forceinline__ void ldsm_x2(uint32_t& r0, uint32_t& r1, uint32_t addr) {
    asm volatile("ldmatrix.sync.aligned.m8n8.x2.shared.b16 {%0,%1}, [%2];"
                 : "=r"(r0), "=r"(r1) : "r"(addr));
}
__device__ __forceinline__ void mma16816(float* c, const uint32_t* a, const uint32_t* b) {
    asm volatile(
        "mma.sync.aligned.m16n8k16.row.col.f32.bf16.bf16.f32 "
        "{%0,%1,%2,%3}, {%4,%5,%6,%7}, {%8,%9}, {%0,%1,%2,%3};"
        : "+f"(c[0]), "+f"(c[1]), "+f"(c[2]), "+f"(c[3])
        : "r"(a[0]), "r"(a[1]), "r"(a[2]), "r"(a[3]), "r"(b[0]), "r"(b[1]));
}

// ---------------- gemm smem geometry ----------------
#define KC     32                 // k elements per stage
#define NIT    (DD / KC)          // 96
#define ROWB   80                 // bytes/row in smem: 32 bf16 (64B) + 16B pad
#define TILEB  (128 * ROWB)       // 10240 B per [128,32] bf16 tile
#define STAGEB (4 * TILEB)        // Ahi, Alo, Bhi, Blo
#define GEMM_SMEM (2 * STAGEB)    // 81920 B double-buffered

// =============================================================================
// bf16x3 HMMA GEMM: out[M,3072] = (Ahi+Alo)[M,3072] @ (Bhi+Blo)[3072,3072]^T + bias
//   B given transposed [N,K]. grid=(N/128, M/128), 256 threads (8 warps 2x4).
// =============================================================================
__global__ void __launch_bounds__(256) gemm_mma(
    const __nv_bfloat16* __restrict__ Ahi, const __nv_bfloat16* __restrict__ Alo,
    const __nv_bfloat16* __restrict__ Bhi, const __nv_bfloat16* __restrict__ Blo,
    const float* __restrict__ bias, float* __restrict__ out,
    int a_gather, int seg, int a_base, int out_scatter, int s_offset)
{
    extern __shared__ char smraw[];
    const uint32_t sb = smem_u32(smraw);
    const int t = threadIdx.x, lane = t & 31, wid = t >> 5;
    const int warp_m = wid & 1, warp_n = wid >> 1;
    const int bm = blockIdx.y << 7, bn = blockIdx.x << 7;

    // cp.async slots: 8 chunks/thread (2 per buffer), 16B each
    const __nv_bfloat16* gsrc[8];
    uint32_t sdst[8];
#pragma unroll
    for (int i = 0; i < 8; i++) {
        int buf = i >> 1;                         // 0 Ahi, 1 Alo, 2 Bhi, 3 Blo
        int c = t + 256 * (i & 1);                // 0..511
        int row = c >> 2, kc = c & 3;
        const __nv_bfloat16* base = (buf == 0) ? Ahi : (buf == 1) ? Alo
                                  : (buf == 2) ? Bhi : Blo;
        long grow;
        if (buf < 2) {
            int m = bm + row;
            grow = a_gather ? ((m / seg) * S_TOT + a_base + (m % seg)) : m;
        } else {
            grow = bn + row;
        }
        gsrc[i] = base + (size_t)grow * DD + kc * 8;
        sdst[i] = sb + buf * TILEB + row * ROWB + kc * 16;
    }

    // ldmatrix per-lane base addresses
    const int lm = lane & 15, lkb = lane >> 4;
    const uint32_t aBase = sb + (warp_m * 64 + lm) * ROWB + lkb * 16;          // Ahi tile
    const int bl = lane & 15;
    const uint32_t bBase = sb + 2 * TILEB + (warp_n * 32 + (bl & 7)) * ROWB + (bl >> 3) * 16;

    float acc[4][4][4];
#pragma unroll
    for (int mf = 0; mf < 4; mf++)
#pragma unroll
        for (int nf = 0; nf < 4; nf++)
#pragma unroll
            for (int r = 0; r < 4; r++) acc[mf][nf][r] = 0.f;

    // prologue: stage 0
    {
#pragma unroll
        for (int i = 0; i < 8; i++) CP_ASYNC16(sdst[i], gsrc[i]);
        CP_COMMIT();
    }

    for (int it = 0; it < NIT; it++) {
        const int s = it & 1;
        if (it + 1 < NIT) {
            const int k0 = (it + 1) * KC;
            const uint32_t so = (s ^ 1) * STAGEB;
#pragma unroll
            for (int i = 0; i < 8; i++) CP_ASYNC16(sdst[i] + so, gsrc[i] + k0);
            CP_COMMIT();
            CP_WAIT(1);
        } else {
            CP_WAIT(0);
        }
        __syncthreads();

        const uint32_t sbase = s * STAGEB;
#pragma unroll
        for (int ks = 0; ks < 2; ks++) {
            uint32_t ah[4][4], al[4][4];
#pragma unroll
            for (int mf = 0; mf < 4; mf++) {
                uint32_t ad = aBase + sbase + mf * (16 * ROWB) + ks * 32;
                ldsm_x4(ah[mf][0], ah[mf][1], ah[mf][2], ah[mf][3], ad);
                ldsm_x4(al[mf][0], al[mf][1], al[mf][2], al[mf][3], ad + TILEB);
            }
            uint32_t bh[4][2], blo[4][2];
#pragma unroll
            for (int nf = 0; nf < 4; nf++) {
                uint32_t bd = bBase + sbase + nf * (8 * ROWB) + ks * 32;
                ldsm_x2(bh[nf][0], bh[nf][1], bd);
                ldsm_x2(blo[nf][0], blo[nf][1], bd + TILEB);
            }
#pragma unroll
            for (int mf = 0; mf < 4; mf++)
#pragma unroll
                for (int nf = 0; nf < 4; nf++) {
                    mma16816(acc[mf][nf], ah[mf], bh[nf]);   // hi*hi
                    mma16816(acc[mf][nf], ah[mf], blo[nf]);  // hi*lo
                    mma16816(acc[mf][nf], al[mf], bh[nf]);   // lo*hi
                }
        }
        __syncthreads();
    }

    // epilogue: bias + (optional) head-scatter.  n-tile == one head (bn>>7).
#pragma unroll
    for (int mf = 0; mf < 4; mf++) {
        const int rbase = bm + warp_m * 64 + mf * 16 + (lane >> 2);
#pragma unroll
        for (int half = 0; half < 2; half++) {
            const int mrow = rbase + half * 8;
            float* orow;
            if (out_scatter) {
                int b = mrow / seg, sl = mrow % seg;
                orow = out + (((size_t)(b * NH + (bn >> 7))) * S_TOT + (s_offset + sl)) * DHD;
            } else {
                orow = out + (size_t)mrow * DD;
            }
#pragma unroll
            for (int nf = 0; nf < 4; nf++) {
                const int col = bn + warp_n * 32 + nf * 8 + (lane & 3) * 2;
                float2 bv = *(const float2*)(bias + col);
                float2 v;
                v.x = acc[mf][nf][half * 2 + 0] + bv.x;
                v.y = acc[mf][nf][half * 2 + 1] + bv.y;
                if (out_scatter) *(float2*)(orow + (col - bn)) = v;
                else             *(float2*)(orow + col) = v;
            }
        }
    }
}

// =============================================================================
// weight transpose + bf16 split: W[K,N] f32 -> Wt hi/lo [N,K] bf16
// =============================================================================
__global__ void __launch_bounds__(256) wsplit_kernel(
    const float* __restrict__ W, __nv_bfloat16* __restrict__ Thi,
    __nv_bfloat16* __restrict__ Tlo)
{
    __shared__ float ts[32][33];
    const int tx = threadIdx.x, ty = threadIdx.y;
    const int n0 = blockIdx.x << 5, k0 = blockIdx.y << 5;
#pragma unroll
    for (int i = 0; i < 4; i++)
        ts[ty + 8 * i][tx] = W[(size_t)(k0 + ty + 8 * i) * DD + n0 + tx];
    __syncthreads();
#pragma unroll
    for (int i = 0; i < 4; i++) {
        float v = ts[tx][ty + 8 * i];
        __nv_bfloat16 h = __float2bfloat16(v);
        float lo = v - __bfloat162float(h);
        size_t o = (size_t)(n0 + ty + 8 * i) * DD + k0 + tx;
        Thi[o] = h;
        Tlo[o] = __float2bfloat16(lo);
    }
}

// =============================================================================
// activation bf16 split
// =============================================================================
__global__ void __launch_bounds__(256) asplit_kernel(
    const float* __restrict__ X, __nv_bfloat16* __restrict__ hi,
    __nv_bfloat16* __restrict__ lo, int n4)
{
    int i = blockIdx.x * 256 + threadIdx.x;
    if (i >= n4) return;
    float4 v = ((const float4*)X)[i];
    __nv_bfloat16 h0 = __float2bfloat16(v.x), h1 = __float2bfloat16(v.y);
    __nv_bfloat16 h2 = __float2bfloat16(v.z), h3 = __float2bfloat16(v.w);
    __nv_bfloat162* hp = (__nv_bfloat162*)hi;
    __nv_bfloat162* lp = (__nv_bfloat162*)lo;
    hp[2 * i + 0] = __nv_bfloat162(h0, h1);
    hp[2 * i + 1] = __nv_bfloat162(h2, h3);
    lp[2 * i + 0] = __nv_bfloat162(__float2bfloat16(v.x - __bfloat162float(h0)),
                                   __float2bfloat16(v.y - __bfloat162float(h1)));
    lp[2 * i + 1] = __nv_bfloat162(__float2bfloat16(v.z - __bfloat162float(h2)),
                                   __float2bfloat16(v.w - __bfloat162float(h3)));
}

// =============================================================================
// RMSNorm + RoPE
// =============================================================================
__global__ void __launch_bounds__(128) norm_rope_kernel(
    float* __restrict__ X,
    const float* __restrict__ g_main, const float* __restrict__ g_add,
    const float* __restrict__ cosI, const float* __restrict__ sinI,
    const float* __restrict__ cosT, const float* __restrict__ sinT)
{
    const int row = blockIdx.x;
    const int s = row % S_TOT;
    const int d = threadIdx.x;
    float x = X[(size_t)row * DHD + d];

    float v = x * x;
#pragma unroll
    for (int off = 16; off > 0; off >>= 1)
        v += __shfl_xor_sync(0xffffffffu, v, off);
    __shared__ float ws[4];
    int lane = d & 31, wid = d >> 5;
    if (lane == 0) ws[wid] = v;
    __syncthreads();
    float tot = ws[0] + ws[1] + ws[2] + ws[3];
    float rn = rsqrtf(tot * (1.f / DHD) + RMS_EPS);

    bool img = (s < S_IMG);
    float g = img ? g_main[d] : g_add[d];
    float xn = x * rn * g;

    int fi = d >> 1;
    int fs = img ? s : (s - S_IMG);
    const float* cp = img ? cosI : cosT;
    const float* sp = img ? sinI : sinT;
    float c = cp[fs * (DHD / 2) + fi];
    float sv = sp[fs * (DHD / 2) + fi];

    float other = __shfl_xor_sync(0xffffffffu, xn, 1);
    float outv = ((d & 1) == 0) ? (xn * c - other * sv)
                                : (other * sv + xn * c);
    X[(size_t)row * DHD + d] = outv;
}

// =============================================================================
// Flash attention fp32 (known-good)
// =============================================================================
#define ATT_SMEM_FLOATS (64*132 + 64*132 + 64*128 + 64*68)

__global__ void __launch_bounds__(256) attn_kernel(
    const float* __restrict__ Q, const float* __restrict__ K,
    const float* __restrict__ V, const int* __restrict__ mask,
    float* __restrict__ O)
{
    extern __shared__ float sm[];
    float* Qs = sm;
    float* Ks = Qs + 64 * 132;
    float* Vs = Ks + 64 * 132;
    float* Ps = Vs + 64 * 128;

    const int tid = threadIdx.x;
    const int tx = tid & 15, ty = tid >> 4;
    const int qt = blockIdx.x;
    const int bh = blockIdx.y;
    const int b = bh / NH, h = bh % NH;
    const int q0 = qt * 64;

    const float* Qb = Q + (size_t)bh * S_TOT * DHD + (size_t)q0 * DHD;
    const float* Kb = K + (size_t)bh * S_TOT * DHD;
    const float* Vb = V + (size_t)bh * S_TOT * DHD;

    for (int idx = tid; idx < 64 * 32; idx += 256) {
        int r = idx >> 5, c4 = (idx & 31) << 2;
        *(float4*)(Qs + r * 132 + c4) = *(const float4*)(Qb + r * DHD + c4);
    }
    __syncthreads();

    float m[4], l[4], o[4][8];
#pragma unroll
    for (int i = 0; i < 4; i++) {
        m[i] = -1e30f; l[i] = 0.f;
#pragma unroll
        for (int c = 0; c < 8; c++) o[i][c] = 0.f;
    }

    for (int kt = 0; kt < S_TOT / 64; kt++) {
        const int k0 = kt * 64;
        for (int idx = tid; idx < 64 * 32; idx += 256) {
            int r = idx >> 5, c4 = (idx & 31) << 2;
            *(float4*)(Ks + r * 132 + c4) = *(const float4*)(Kb + (size_t)(k0 + r) * DHD + c4);
            *(float4*)(Vs + r * 128 + c4) = *(const float4*)(Vb + (size_t)(k0 + r) * DHD + c4);
        }
        __syncthreads();

        float s[4][4];
#pragma unroll
        for (int i = 0; i < 4; i++)
#pragma unroll
            for (int j = 0; j < 4; j++) s[i][j] = 0.f;

        for (int d = 0; d < DHD; d += 4) {
            float4 a[4], bq[4];
#pragma unroll
            for (int i = 0; i < 4; i++) a[i] = *(const float4*)(Qs + (ty + 16 * i) * 132 + d);
#pragma unroll
            for (int j = 0; j < 4; j++) bq[j] = *(const float4*)(Ks + (tx + 16 * j) * 132 + d);
#pragma unroll
            for (int i = 0; i < 4; i++)
#pragma unroll
                for (int j = 0; j < 4; j++)
                    s[i][j] += a[i].x * bq[j].x + a[i].y * bq[j].y +
                               a[i].z * bq[j].z + a[i].w * bq[j].w;
        }

#pragma unroll
        for (int j = 0; j < 4; j++) {
            int kg = k0 + tx + 16 * j;
            float biasv = 0.f;
            if (kg >= S_IMG && mask[b * S_TXT + (kg - S_IMG)] == 0) biasv = -1e9f;
#pragma unroll
            for (int i = 0; i < 4; i++) s[i][j] = s[i][j] * ATT_SCALE + biasv;
        }

#pragma unroll
        for (int i = 0; i < 4; i++) {
            float mt = fmaxf(fmaxf(s[i][0], s[i][1]), fmaxf(s[i][2], s[i][3]));
            mt = fmaxf(mt, __shfl_xor_sync(0xffffffffu, mt, 8));
            mt = fmaxf(mt, __shfl_xor_sync(0xffffffffu, mt, 4));
            mt = fmaxf(mt, __shfl_xor_sync(0xffffffffu, mt, 2));
            mt = fmaxf(mt, __shfl_xor_sync(0xffffffffu, mt, 1));
            float mn = fmaxf(m[i], mt);
            float al = __expf(m[i] - mn);
            float rs = 0.f;
#pragma unroll
            for (int j = 0; j < 4; j++) {
                float p = __expf(s[i][j] - mn);
                Ps[(ty + 16 * i) * 68 + tx + 16 * j] = p;
                rs += p;
            }
            rs += __shfl_xor_sync(0xffffffffu, rs, 8);
            rs += __shfl_xor_sync(0xffffffffu, rs, 4);
            rs += __shfl_xor_sync(0xffffffffu, rs, 2);
            rs += __shfl_xor_sync(0xffffffffu, rs, 1);
            l[i] = l[i] * al + rs;
            m[i] = mn;
#pragma unroll
            for (int c = 0; c < 8; c++) o[i][c] *= al;
        }
        __syncthreads();

        for (int k = 0; k < 64; k++) {
            float4 v0 = *(const float4*)(Vs + k * 128 + 4 * tx);
            float4 v1 = *(const float4*)(Vs + k * 128 + 64 + 4 * tx);
#pragma unroll
            for (int i = 0; i < 4; i++) {
                float a = Ps[(ty + 16 * i) * 68 + k];
                o[i][0] += a * v0.x; o[i][1] += a * v0.y;
                o[i][2] += a * v0.z; o[i][3] += a * v0.w;
                o[i][4] += a * v1.x; o[i][5] += a * v1.y;
                o[i][6] += a * v1.z; o[i][7] += a * v1.w;
            }
        }
        __syncthreads();
    }

#pragma unroll
    for (int i = 0; i < 4; i++) {
        float inv = 1.f / l[i];
        int sg = q0 + ty + 16 * i;
        float* op = O + ((size_t)(b * S_TOT + sg)) * DD + h * DHD;
        float4 r0 = make_float4(o[i][0] * inv, o[i][1] * inv, o[i][2] * inv, o[i][3] * inv);
        float4 r1 = make_float4(o[i][4] * inv, o[i][5] * inv, o[i][6] * inv, o[i][7] * inv);
        *(float4*)(op + 4 * tx) = r0;
        *(float4*)(op + 64 + 4 * tx) = r1;
    }
}

// =============================================================================
// Launch
// =============================================================================
extern "C" void kernel_launch(void* const* d_in, const int* in_sizes, int n_in,
                              void* d_out, int out_size)
{
    const float* hidden = (const float*)d_in[0];
    const float* enc    = (const float*)d_in[1];
    const int*   mask   = (const int*)d_in[2];
    const int fb = (in_sizes[3] == 2) ? 4 : 3;
    const float* cosI = (const float*)d_in[fb + 0];
    const float* sinI = (const float*)d_in[fb + 1];
    const float* cosT = (const float*)d_in[fb + 2];
    const float* sinT = (const float*)d_in[fb + 3];
    const float* W[8]  = { (const float*)d_in[8],  (const float*)d_in[10],
                           (const float*)d_in[12], (const float*)d_in[14],
                           (const float*)d_in[16], (const float*)d_in[18],
                           (const float*)d_in[20], (const float*)d_in[22] };
    const float* bq     = (const float*)d_in[9];
    const float* bk     = (const float*)d_in[11];
    const float* bv     = (const float*)d_in[13];
    const float* bq_add = (const float*)d_in[15];
    const float* bk_add = (const float*)d_in[17];
    const float* bv_add = (const float*)d_in[19];
    const float* bo     = (const float*)d_in[21];
    const float* bo_add = (const float*)d_in[23];
    const float* gq     = (const float*)d_in[24];
    const float* gk     = (const float*)d_in[25];
    const float* gq_add = (const float*)d_in[26];
    const float* gk_add = (const float*)d_in[27];

    float* out = (float*)d_out;

    float *Qp, *Kp, *Vp, *Op;
    cudaGetSymbolAddress((void**)&Qp, g_Q);
    cudaGetSymbolAddress((void**)&Kp, g_K);
    cudaGetSymbolAddress((void**)&Vp, g_V);
    cudaGetSymbolAddress((void**)&Op, g_O);
    __nv_bfloat16 *Whi, *Wlo, *Hhi, *Hlo, *Ehi, *Elo, *Shi, *Slo;
    cudaGetSymbolAddress((void**)&Whi, g_Whi);
    cudaGetSymbolAddress((void**)&Wlo, g_Wlo);
    cudaGetSymbolAddress((void**)&Hhi, g_Hhi);
    cudaGetSymbolAddress((void**)&Hlo, g_Hlo);
    cudaGetSymbolAddress((void**)&Ehi, g_Ehi);
    cudaGetSymbolAddress((void**)&Elo, g_Elo);
    cudaGetSymbolAddress((void**)&Shi, g_Shi);
    cudaGetSymbolAddress((void**)&Slo, g_Slo);

    cudaFuncSetAttribute(gemm_mma, cudaFuncAttributeMaxDynamicSharedMemorySize, GEMM_SMEM);
    const size_t attn_smem = ATT_SMEM_FLOATS * sizeof(float);
    cudaFuncSetAttribute(attn_kernel, cudaFuncAttributeMaxDynamicSharedMemorySize, (int)attn_smem);

    // 1) weight transpose+split, activation split
    dim3 wgrid(DD / 32, DD / 32);
    for (int i = 0; i < 8; i++)
        wsplit_kernel<<<wgrid, dim3(32, 8)>>>(W[i], Whi + (size_t)i * DD * DD,
                                              Wlo + (size_t)i * DD * DD);
    asplit_kernel<<<(M_IMG * DD / 4 + 255) / 256, 256>>>(hidden, Hhi, Hlo, M_IMG * DD / 4);
    asplit_kernel<<<(M_TXT * DD / 4 + 255) / 256, 256>>>(enc, Ehi, Elo, M_TXT * DD / 4);

    // 2) QKV projections (HMMA), scatter into [B,H,S,DH]
    dim3 gi(DD / 128, M_IMG / 128), gt(DD / 128, M_TXT / 128);
    const size_t WN = (size_t)DD * DD;
    gemm_mma<<<gi, 256, GEMM_SMEM>>>(Hhi, Hlo, Whi + 0 * WN, Wlo + 0 * WN, bq, Qp, 0, S_IMG, 0, 1, 0);
    gemm_mma<<<gi, 256, GEMM_SMEM>>>(Hhi, Hlo, Whi + 1 * WN, Wlo + 1 * WN, bk, Kp, 0, S_IMG, 0, 1, 0);
    gemm_mma<<<gi, 256, GEMM_SMEM>>>(Hhi, Hlo, Whi + 2 * WN, Wlo + 2 * WN, bv, Vp, 0, S_IMG, 0, 1, 0);
    gemm_mma<<<gt, 256, GEMM_SMEM>>>(Ehi, Elo, Whi + 3 * WN, Wlo + 3 * WN, bq_add, Qp, 0, S_TXT, 0, 1, S_IMG);
    gemm_mma<<<gt, 256, GEMM_SMEM>>>(Ehi, Elo, Whi + 4 * WN, Wlo + 4 * WN, bk_add, Kp, 0, S_TXT, 0, 1, S_IMG);
    gemm_mma<<<gt, 256, GEMM_SMEM>>>(Ehi, Elo, Whi + 5 * WN, Wlo + 5 * WN, bv_add, Vp, 0, S_TXT, 0, 1, S_IMG);

    // 3) RMSNorm + RoPE
    int nrows = BB * NH * S_TOT;
    norm_rope_kernel<<<nrows, 128>>>(Qp, gq, gq_add, cosI, sinI, cosT, sinT);
    norm_rope_kernel<<<nrows, 128>>>(Kp, gk, gk_add, cosI, sinI, cosT, sinT);

    // 4) attention
    attn_kernel<<<dim3(S_TOT / 64, BB * NH), 256, attn_smem>>>(Qp, Kp, Vp, mask, Op);

    // 5) split attention output, then output projections (HMMA)
    asplit_kernel<<<(M_O * DD / 4 + 255) / 256, 256>>>(Op, Shi, Slo, M_O * DD / 4);
    gemm_mma<<<gi, 256, GEMM_SMEM>>>(Shi, Slo, Whi + 6 * WN, Wlo + 6 * WN, bo, out, 1, S_IMG, 0, 0, 0);
    gemm_mma<<<gt, 256, GEMM_SMEM>>>(Shi, Slo, Whi + 7 * WN, Wlo + 7 * WN, bo_add,
                                     out + IMG_OUT_ELEMS, 1, S_TXT, S_IMG, 0, 0);
}

// round 7
// speedup vs baseline: 2.9503x; 1.7098x over previous
#include <cuda_runtime.h>
#include <cuda_bf16.h>
#include <math.h>
#include <stdint.h>

// ---------------- problem constants ----------------
#define BB     2
#define S_IMG  2048
#define S_TXT  256
#define S_TOT  2304
#define NH     24
#define DHD    128
#define DD     3072
#define ATT_SCALE 0.08838834764831845f
#define RMS_EPS   1e-5f

#define M_IMG  (BB * S_IMG)          // 4096
#define M_TXT  (BB * S_TXT)          // 512
#define M_O    (BB * S_TOT)          // 4608
#define IMG_OUT_ELEMS (M_IMG * DD)

// ---------------- device scratch ----------------
__device__ float g_Q[BB * NH * S_TOT * DHD];   // fp32 [B,H,S,DH] from projections
__device__ float g_K[BB * NH * S_TOT * DHD];
__device__ float g_V[BB * NH * S_TOT * DHD];

__device__ __nv_bfloat16 g_Qh[BB * NH * S_TOT * DHD], g_Ql[BB * NH * S_TOT * DHD];
__device__ __nv_bfloat16 g_Kh[BB * NH * S_TOT * DHD], g_Kl[BB * NH * S_TOT * DHD];
__device__ __nv_bfloat16 g_Vh[BB * NH * S_TOT * DHD], g_Vl[BB * NH * S_TOT * DHD];

__device__ __nv_bfloat16 g_Whi[8][DD * DD];   // transposed [N,K] bf16 hi
__device__ __nv_bfloat16 g_Wlo[8][DD * DD];   // transposed [N,K] bf16 lo
__device__ __nv_bfloat16 g_Hhi[M_IMG * DD], g_Hlo[M_IMG * DD];
__device__ __nv_bfloat16 g_Ehi[M_TXT * DD], g_Elo[M_TXT * DD];
__device__ __nv_bfloat16 g_Shi[M_O * DD],  g_Slo[M_O * DD];   // attn-out split [B,S,D]

// ---------------- PTX helpers ----------------
__device__ __forceinline__ uint32_t smem_u32(const void* p) {
    uint32_t a;
    asm("{ .reg .u64 t; cvta.to.shared.u64 t, %1; cvt.u32.u64 %0, t; }" : "=r"(a) : "l"(p));
    return a;
}
#define CP_ASYNC16(sa, gp) \
    asm volatile("cp.async.cg.shared.global [%0], [%1], 16;" :: "r"(sa), "l"(gp) : "memory")
#define CP_COMMIT() asm volatile("cp.async.commit_group;" ::: "memory")
#define CP_WAIT(n)  asm volatile("cp.async.wait_group %0;" :: "n"(n) : "memory")

__device__ __forceinline__ void ldsm_x4(uint32_t& r0, uint32_t& r1, uint32_t& r2,
                                        uint32_t& r3, uint32_t addr) {
    asm volatile("ldmatrix.sync.aligned.m8n8.x4.shared.b16 {%0,%1,%2,%3}, [%4];"
                 : "=r"(r0), "=r"(r1), "=r"(r2), "=r"(r3) : "r"(addr));
}
__device__ __forceinline__ void ldsm_x4_t(uint32_t& r0, uint32_t& r1, uint32_t& r2,
                                          uint32_t& r3, uint32_t addr) {
    asm volatile("ldmatrix.sync.aligned.m8n8.x4.trans.shared.b16 {%0,%1,%2,%3}, [%4];"
                 : "=r"(r0), "=r"(r1), "=r"(r2), "=r"(r3) : "r"(addr));
}
__device__ __forceinline__ void ldsm_x2(uint32_t& r0, uint32_t& r1, uint32_t addr) {
    asm volatile("ldmatrix.sync.aligned.m8n8.x2.shared.b16 {%0,%1}, [%2];"
                 : "=r"(r0), "=r"(r1) : "r"(addr));
}
__device__ __forceinline__ void mma16816(float* c, const uint32_t* a, const uint32_t* b) {
    asm volatile(
        "mma.sync.aligned.m16n8k16.row.col.f32.bf16.bf16.f32 "
        "{%0,%1,%2,%3}, {%4,%5,%6,%7}, {%8,%9}, {%0,%1,%2,%3};"
        : "+f"(c[0]), "+f"(c[1]), "+f"(c[2]), "+f"(c[3])
        : "r"(a[0]), "r"(a[1]), "r"(a[2]), "r"(a[3]), "r"(b[0]), "r"(b[1]));
}
// pack two f32 -> bf16x2 (low = a, high = b)
__device__ __forceinline__ uint32_t pack_bf2(float a, float b) {
    uint32_t r;
    asm("cvt.rn.bf16x2.f32 %0, %1, %2;" : "=r"(r) : "f"(b), "f"(a));
    return r;
}

// ---------------- gemm smem geometry ----------------
#define KC     32
#define NIT    (DD / KC)          // 96
#define ROWB   80
#define TILEB  (128 * ROWB)
#define STAGEB (4 * TILEB)
#define GEMM_SMEM (2 * STAGEB)

// =============================================================================
// bf16x3 HMMA GEMM (unchanged, known-good from R6)
// =============================================================================
__global__ void __launch_bounds__(256) gemm_mma(
    const __nv_bfloat16* __restrict__ Ahi, const __nv_bfloat16* __restrict__ Alo,
    const __nv_bfloat16* __restrict__ Bhi, const __nv_bfloat16* __restrict__ Blo,
    const float* __restrict__ bias, float* __restrict__ out,
    int a_gather, int seg, int a_base, int out_scatter, int s_offset)
{
    extern __shared__ char smraw[];
    const uint32_t sb = smem_u32(smraw);
    const int t = threadIdx.x, lane = t & 31, wid = t >> 5;
    const int warp_m = wid & 1, warp_n = wid >> 1;
    const int bm = blockIdx.y << 7, bn = blockIdx.x << 7;

    const __nv_bfloat16* gsrc[8];
    uint32_t sdst[8];
#pragma unroll
    for (int i = 0; i < 8; i++) {
        int buf = i >> 1;
        int c = t + 256 * (i & 1);
        int row = c >> 2, kc = c & 3;
        const __nv_bfloat16* base = (buf == 0) ? Ahi : (buf == 1) ? Alo
                                  : (buf == 2) ? Bhi : Blo;
        long grow;
        if (buf < 2) {
            int m = bm + row;
            grow = a_gather ? ((m / seg) * S_TOT + a_base + (m % seg)) : m;
        } else {
            grow = bn + row;
        }
        gsrc[i] = base + (size_t)grow * DD + kc * 8;
        sdst[i] = sb + buf * TILEB + row * ROWB + kc * 16;
    }

    const int lm = lane & 15, lkb = lane >> 4;
    const uint32_t aBase = sb + (warp_m * 64 + lm) * ROWB + lkb * 16;
    const int bl = lane & 15;
    const uint32_t bBase = sb + 2 * TILEB + (warp_n * 32 + (bl & 7)) * ROWB + (bl >> 3) * 16;

    float acc[4][4][4];
#pragma unroll
    for (int mf = 0; mf < 4; mf++)
#pragma unroll
        for (int nf = 0; nf < 4; nf++)
#pragma unroll
            for (int r = 0; r < 4; r++) acc[mf][nf][r] = 0.f;

    {
#pragma unroll
        for (int i = 0; i < 8; i++) CP_ASYNC16(sdst[i], gsrc[i]);
        CP_COMMIT();
    }

    for (int it = 0; it < NIT; it++) {
        const int s = it & 1;
        if (it + 1 < NIT) {
            const int k0 = (it + 1) * KC;
            const uint32_t so = (s ^ 1) * STAGEB;
#pragma unroll
            for (int i = 0; i < 8; i++) CP_ASYNC16(sdst[i] + so, gsrc[i] + k0);
            CP_COMMIT();
            CP_WAIT(1);
        } else {
            CP_WAIT(0);
        }
        __syncthreads();

        const uint32_t sbase = s * STAGEB;
#pragma unroll
        for (int ks = 0; ks < 2; ks++) {
            uint32_t ah[4][4], al[4][4];
#pragma unroll
            for (int mf = 0; mf < 4; mf++) {
                uint32_t ad = aBase + sbase + mf * (16 * ROWB) + ks * 32;
                ldsm_x4(ah[mf][0], ah[mf][1], ah[mf][2], ah[mf][3], ad);
                ldsm_x4(al[mf][0], al[mf][1], al[mf][2], al[mf][3], ad + TILEB);
            }
            uint32_t bh[4][2], blo[4][2];
#pragma unroll
            for (int nf = 0; nf < 4; nf++) {
                uint32_t bd = bBase + sbase + nf * (8 * ROWB) + ks * 32;
                ldsm_x2(bh[nf][0], bh[nf][1], bd);
                ldsm_x2(blo[nf][0], blo[nf][1], bd + TILEB);
            }
#pragma unroll
            for (int mf = 0; mf < 4; mf++)
#pragma unroll
                for (int nf = 0; nf < 4; nf++) {
                    mma16816(acc[mf][nf], ah[mf], bh[nf]);
                    mma16816(acc[mf][nf], ah[mf], blo[nf]);
                    mma16816(acc[mf][nf], al[mf], bh[nf]);
                }
        }
        __syncthreads();
    }

#pragma unroll
    for (int mf = 0; mf < 4; mf++) {
        const int rbase = bm + warp_m * 64 + mf * 16 + (lane >> 2);
#pragma unroll
        for (int half = 0; half < 2; half++) {
            const int mrow = rbase + half * 8;
            float* orow;
            if (out_scatter) {
                int b = mrow / seg, sl = mrow % seg;
                orow = out + (((size_t)(b * NH + (bn >> 7))) * S_TOT + (s_offset + sl)) * DHD;
            } else {
                orow = out + (size_t)mrow * DD;
            }
#pragma unroll
            for (int nf = 0; nf < 4; nf++) {
                const int col = bn + warp_n * 32 + nf * 8 + (lane & 3) * 2;
                float2 bv = *(const float2*)(bias + col);
                float2 v;
                v.x = acc[mf][nf][half * 2 + 0] + bv.x;
                v.y = acc[mf][nf][half * 2 + 1] + bv.y;
                if (out_scatter) *(float2*)(orow + (col - bn)) = v;
                else             *(float2*)(orow + col) = v;
            }
        }
    }
}

// =============================================================================
// weight transpose + bf16 split
// =============================================================================
__global__ void __launch_bounds__(256) wsplit_kernel(
    const float* __restrict__ W, __nv_bfloat16* __restrict__ Thi,
    __nv_bfloat16* __restrict__ Tlo)
{
    __shared__ float ts[32][33];
    const int tx = threadIdx.x, ty = threadIdx.y;
    const int n0 = blockIdx.x << 5, k0 = blockIdx.y << 5;
#pragma unroll
    for (int i = 0; i < 4; i++)
        ts[ty + 8 * i][tx] = W[(size_t)(k0 + ty + 8 * i) * DD + n0 + tx];
    __syncthreads();
#pragma unroll
    for (int i = 0; i < 4; i++) {
        float v = ts[tx][ty + 8 * i];
        __nv_bfloat16 h = __float2bfloat16(v);
        float lo = v - __bfloat162float(h);
        size_t o = (size_t)(n0 + ty + 8 * i) * DD + k0 + tx;
        Thi[o] = h;
        Tlo[o] = __float2bfloat16(lo);
    }
}

// =============================================================================
// elementwise bf16 split
// =============================================================================
__global__ void __launch_bounds__(256) asplit_kernel(
    const float* __restrict__ X, __nv_bfloat16* __restrict__ hi,
    __nv_bfloat16* __restrict__ lo, int n4)
{
    int i = blockIdx.x * 256 + threadIdx.x;
    if (i >= n4) return;
    float4 v = ((const float4*)X)[i];
    __nv_bfloat16 h0 = __float2bfloat16(v.x), h1 = __float2bfloat16(v.y);
    __nv_bfloat16 h2 = __float2bfloat16(v.z), h3 = __float2bfloat16(v.w);
    __nv_bfloat162* hp = (__nv_bfloat162*)hi;
    __nv_bfloat162* lp = (__nv_bfloat162*)lo;
    hp[2 * i + 0] = __nv_bfloat162(h0, h1);
    hp[2 * i + 1] = __nv_bfloat162(h2, h3);
    lp[2 * i + 0] = __nv_bfloat162(__float2bfloat16(v.x - __bfloat162float(h0)),
                                   __float2bfloat16(v.y - __bfloat162float(h1)));
    lp[2 * i + 1] = __nv_bfloat162(__float2bfloat16(v.z - __bfloat162float(h2)),
                                   __float2bfloat16(v.w - __bfloat162float(h3)));
}

// =============================================================================
// RMSNorm + RoPE + bf16 split (Q/K): fp32 in, hi/lo bf16 out
// =============================================================================
__global__ void __launch_bounds__(128) norm_rope_split(
    const float* __restrict__ X,
    __nv_bfloat16* __restrict__ Xh, __nv_bfloat16* __restrict__ Xl,
    const float* __restrict__ g_main, const float* __restrict__ g_add,
    const float* __restrict__ cosI, const float* __restrict__ sinI,
    const float* __restrict__ cosT, const float* __restrict__ sinT)
{
    const int row = blockIdx.x;
    const int s = row % S_TOT;
    const int d = threadIdx.x;
    float x = X[(size_t)row * DHD + d];

    float v = x * x;
#pragma unroll
    for (int off = 16; off > 0; off >>= 1)
        v += __shfl_xor_sync(0xffffffffu, v, off);
    __shared__ float ws[4];
    int lane = d & 31, wid = d >> 5;
    if (lane == 0) ws[wid] = v;
    __syncthreads();
    float tot = ws[0] + ws[1] + ws[2] + ws[3];
    float rn = rsqrtf(tot * (1.f / DHD) + RMS_EPS);

    bool img = (s < S_IMG);
    float g = img ? g_main[d] : g_add[d];
    float xn = x * rn * g;

    int fi = d >> 1;
    int fs = img ? s : (s - S_IMG);
    const float* cp = img ? cosI : cosT;
    const float* sp = img ? sinI : sinT;
    float c = cp[fs * (DHD / 2) + fi];
    float sv = sp[fs * (DHD / 2) + fi];

    float other = __shfl_xor_sync(0xffffffffu, xn, 1);
    float outv = ((d & 1) == 0) ? (xn * c - other * sv)
                                : (other * sv + xn * c);
    __nv_bfloat16 hb = __float2bfloat16(outv);
    Xh[(size_t)row * DHD + d] = hb;
    Xl[(size_t)row * DHD + d] = __float2bfloat16(outv - __bfloat162float(hb));
}

// =============================================================================
// HMMA flash attention, bf16x3 on both GEMMs, P kept in registers.
// CTA: 256 thr (8 warps), 128 q rows (16/warp), BK=64, DH=128.
// K/V cp.async double-buffered. Writes hi/lo bf16 output [B,S,D].
// =============================================================================
#define SPAD  136                  // bf16 elems per smem row (272 B)
#define SPB   272
#define ATSB  (64 * SPB)           // one K/V tile, bytes = 17408
#define AQB   (128 * SPB)          // one Q tile, bytes = 34816
#define SM_QH 0
#define SM_QL AQB
#define SM_ST0 (2 * AQB)           // 69632
#define SM_STSZ (4 * ATSB)         // 69632 per stage
#define SM_BIAS (SM_ST0 + 2 * SM_STSZ)      // 208896
#define ATT_SMEM (SM_BIAS + S_TXT * 4)      // 209920 B
#define NKT (S_TOT / 64)           // 36

__global__ void __launch_bounds__(256, 1) attn_mma(
    const __nv_bfloat16* __restrict__ Qh, const __nv_bfloat16* __restrict__ Ql,
    const __nv_bfloat16* __restrict__ Kh, const __nv_bfloat16* __restrict__ Kl,
    const __nv_bfloat16* __restrict__ Vh, const __nv_bfloat16* __restrict__ Vl,
    const int* __restrict__ mask,
    __nv_bfloat16* __restrict__ Ohi, __nv_bfloat16* __restrict__ Olo)
{
    extern __shared__ char smraw[];
    const uint32_t sb = smem_u32(smraw);
    const int t = threadIdx.x, lane = t & 31, w = t >> 5;
    const int bh = blockIdx.y, b = bh / NH, h = bh % NH;
    const int q0 = blockIdx.x * 128;
    const size_t bhoff = (size_t)bh * S_TOT * DHD;

    // mask bias to smem
    if (t < S_TXT)
        *(float*)(smraw + SM_BIAS + t * 4) = (mask[b * S_TXT + t] == 0) ? -1e9f : 0.f;

    // K/V cp.async slot setup: 16 chunks/thread/stage
    const __nv_bfloat16* kvsrc[4] = { Kh + bhoff, Kl + bhoff, Vh + bhoff, Vl + bhoff };
    // issue stage for tile kt into stage s
    auto issue = [&](int kt, int s) {
        const uint32_t stb = sb + SM_ST0 + s * SM_STSZ;
        const int k0 = kt * 64;
#pragma unroll
        for (int c = 0; c < 16; c++) {
            int buf = c >> 2;
            int idx = t + 256 * (c & 3);
            int row = idx >> 4, ch = idx & 15;
            const __nv_bfloat16* gp = kvsrc[buf] + (size_t)(k0 + row) * DHD + ch * 8;
            uint32_t sa = stb + buf * ATSB + row * SPB + ch * 16;
            CP_ASYNC16(sa, gp);
        }
    };

    issue(0, 0);
    CP_COMMIT();

    // Q load (plain), hi+lo: 4096 16B-chunks, 16/thread
    {
        const __nv_bfloat16* qsrc[2] = { Qh + bhoff + (size_t)q0 * DHD,
                                         Ql + bhoff + (size_t)q0 * DHD };
#pragma unroll
        for (int i = 0; i < 16; i++) {
            int idx = t + 256 * i;
            int buf = idx >> 11, rem = idx & 2047;
            int row = rem >> 4, ch = rem & 15;
            uint4 v = *(const uint4*)(qsrc[buf] + (size_t)row * DHD + ch * 8);
            *(uint4*)(smraw + buf * AQB + row * SPB + ch * 16) = v;
        }
    }

    // ldmatrix base addrs
    const uint32_t qA = sb + SM_QH + (w * 16 + (lane & 15)) * SPB + (lane >> 4) * 16;
    const uint32_t kBrel = ((lane >> 4) * 8 + (lane & 7)) * SPB + ((lane >> 3) & 1) * 16;
    const uint32_t vBrel = (lane & 15) * SPB + (lane >> 4) * 16;

    float m0 = -1e30f, m1 = -1e30f, l0 = 0.f, l1 = 0.f;
    float o[16][4];
#pragma unroll
    for (int nf = 0; nf < 16; nf++)
#pragma unroll
        for (int e = 0; e < 4; e++) o[nf][e] = 0.f;

    for (int kt = 0; kt < NKT; kt++) {
        const int s = kt & 1;
        if (kt + 1 < NKT) { issue(kt + 1, s ^ 1); CP_COMMIT(); CP_WAIT(1); }
        else             { CP_WAIT(0); }
        __syncthreads();

        const uint32_t stb = sb + SM_ST0 + s * SM_STSZ;

        // ---- QK^T (3-pass bf16) -> sc[8][4] fp32
        float sc[8][4];
#pragma unroll
        for (int j = 0; j < 8; j++)
#pragma unroll
            for (int e = 0; e < 4; e++) sc[j][e] = 0.f;

#pragma unroll
        for (int ks = 0; ks < 8; ks++) {
            uint32_t qh[4], ql[4];
            ldsm_x4(qh[0], qh[1], qh[2], qh[3], qA + ks * 32);
            ldsm_x4(ql[0], ql[1], ql[2], ql[3], qA + AQB + ks * 32);
#pragma unroll
            for (int j2 = 0; j2 < 4; j2++) {
                uint32_t kb[4], klr[4];
                uint32_t kd = stb + kBrel + j2 * (16 * SPB) + ks * 32;
                ldsm_x4(kb[0], kb[1], kb[2], kb[3], kd);
                ldsm_x4(klr[0], klr[1], klr[2], klr[3], kd + ATSB);
                mma16816(sc[2 * j2 + 0], qh, kb);
                mma16816(sc[2 * j2 + 1], qh, kb + 2);
                mma16816(sc[2 * j2 + 0], qh, klr);
                mma16816(sc[2 * j2 + 1], qh, klr + 2);
                mma16816(sc[2 * j2 + 0], ql, kb);
                mma16816(sc[2 * j2 + 1], ql, kb + 2);
            }
        }

        // ---- scale + mask bias
        const bool txt_tile = (kt * 64 + 63 >= S_IMG);
#pragma unroll
        for (int j = 0; j < 8; j++) {
            int colb = kt * 64 + j * 8 + (lane & 3) * 2;
            float b0v = 0.f, b1v = 0.f;
            if (txt_tile) {
                if (colb + 0 >= S_IMG) b0v = *(float*)(smraw + SM_BIAS + (colb + 0 - S_IMG) * 4);
                if (colb + 1 >= S_IMG) b1v = *(float*)(smraw + SM_BIAS + (colb + 1 - S_IMG) * 4);
            }
            sc[j][0] = sc[j][0] * ATT_SCALE + b0v;
            sc[j][1] = sc[j][1] * ATT_SCALE + b1v;
            sc[j][2] = sc[j][2] * ATT_SCALE + b0v;
            sc[j][3] = sc[j][3] * ATT_SCALE + b1v;
        }

        // ---- online softmax (rows g = lane>>2 and g+8, warp-local)
        float mx0 = -1e30f, mx1 = -1e30f;
#pragma unroll
        for (int j = 0; j < 8; j++) {
            mx0 = fmaxf(mx0, fmaxf(sc[j][0], sc[j][1]));
            mx1 = fmaxf(mx1, fmaxf(sc[j][2], sc[j][3]));
        }
        mx0 = fmaxf(mx0, __shfl_xor_sync(0xffffffffu, mx0, 1));
        mx0 = fmaxf(mx0, __shfl_xor_sync(0xffffffffu, mx0, 2));
        mx1 = fmaxf(mx1, __shfl_xor_sync(0xffffffffu, mx1, 1));
        mx1 = fmaxf(mx1, __shfl_xor_sync(0xffffffffu, mx1, 2));
        float mn0 = fmaxf(m0, mx0), mn1 = fmaxf(m1, mx1);
        float al0 = __expf(m0 - mn0), al1 = __expf(m1 - mn1);
        float rs0 = 0.f, rs1 = 0.f;
#pragma unroll
        for (int j = 0; j < 8; j++) {
            sc[j][0] = __expf(sc[j][0] - mn0); rs0 += sc[j][0];
            sc[j][1] = __expf(sc[j][1] - mn0); rs0 += sc[j][1];
            sc[j][2] = __expf(sc[j][2] - mn1); rs1 += sc[j][2];
            sc[j][3] = __expf(sc[j][3] - mn1); rs1 += sc[j][3];
        }
        rs0 += __shfl_xor_sync(0xffffffffu, rs0, 1);
        rs0 += __shfl_xor_sync(0xffffffffu, rs0, 2);
        rs1 += __shfl_xor_sync(0xffffffffu, rs1, 1);
        rs1 += __shfl_xor_sync(0xffffffffu, rs1, 2);
        l0 = l0 * al0 + rs0; m0 = mn0;
        l1 = l1 * al1 + rs1; m1 = mn1;
#pragma unroll
        for (int nf = 0; nf < 16; nf++) {
            o[nf][0] *= al0; o[nf][1] *= al0;
            o[nf][2] *= al1; o[nf][3] *= al1;
        }

        // ---- P @ V (3-pass): P frags direct from sc (no smem roundtrip)
        const uint32_t vtb = stb + 2 * ATSB;
#pragma unroll
        for (int ksv = 0; ksv < 4; ksv++) {
            uint32_t ah[4], alr[4];
#pragma unroll
            for (int q = 0; q < 4; q++) {
                int j = 2 * ksv + (q >> 1);
                float pa = sc[j][(q & 1) * 2 + 0];
                float pb = sc[j][(q & 1) * 2 + 1];
                uint32_t hp = pack_bf2(pa, pb);
                ah[q] = hp;
                float ha = __uint_as_float((hp & 0xffffu) << 16);
                float hb2 = __uint_as_float(hp & 0xffff0000u);
                alr[q] = pack_bf2(pa - ha, pb - hb2);
            }
            // note: a-frag order must be {a0,a1,a2,a3} = {j=2ksv e01, j=2ksv e23, j=2ksv+1 e01, j=2ksv+1 e23}
            uint32_t aH[4] = { ah[0], ah[1], ah[2], ah[3] };
            uint32_t aL[4] = { alr[0], alr[1], alr[2], alr[3] };
#pragma unroll
            for (int ch = 0; ch < 8; ch++) {
                uint32_t vb[4], vlr[4];
                uint32_t vd = vtb + vBrel + ksv * (16 * SPB) + ch * 32;
                ldsm_x4_t(vb[0], vb[1], vb[2], vb[3], vd);
                ldsm_x4_t(vlr[0], vlr[1], vlr[2], vlr[3], vd + ATSB);
                mma16816(o[2 * ch + 0], aH, vb);
                mma16816(o[2 * ch + 1], aH, vb + 2);
                mma16816(o[2 * ch + 0], aH, vlr);
                mma16816(o[2 * ch + 1], aH, vlr + 2);
                mma16816(o[2 * ch + 0], aL, vb);
                mma16816(o[2 * ch + 1], aL, vb + 2);
            }
        }
        __syncthreads();
    }

    // ---- epilogue: normalize, split hi/lo, write [B,S,D]
    float inv0 = 1.f / l0, inv1 = 1.f / l1;
    int r0 = q0 + w * 16 + (lane >> 2), r1 = r0 + 8;
    size_t base0 = ((size_t)(b * S_TOT + r0)) * DD + h * DHD;
    size_t base1 = ((size_t)(b * S_TOT + r1)) * DD + h * DHD;
#pragma unroll
    for (int nf = 0; nf < 16; nf++) {
        int d = nf * 8 + (lane & 3) * 2;
        float v0 = o[nf][0] * inv0, v1 = o[nf][1] * inv0;
        uint32_t hp = pack_bf2(v0, v1);
        *(uint32_t*)((char*)Ohi + (base0 + d) * 2) = hp;
        float ha = __uint_as_float((hp & 0xffffu) << 16);
        float hb2 = __uint_as_float(hp & 0xffff0000u);
        *(uint32_t*)((char*)Olo + (base0 + d) * 2) = pack_bf2(v0 - ha, v1 - hb2);

        float u0 = o[nf][2] * inv1, u1 = o[nf][3] * inv1;
        uint32_t hq = pack_bf2(u0, u1);
        *(uint32_t*)((char*)Ohi + (base1 + d) * 2) = hq;
        float hc = __uint_as_float((hq & 0xffffu) << 16);
        float hd = __uint_as_float(hq & 0xffff0000u);
        *(uint32_t*)((char*)Olo + (base1 + d) * 2) = pack_bf2(u0 - hc, u1 - hd);
    }
}

// =============================================================================
// Launch
// =============================================================================
extern "C" void kernel_launch(void* const* d_in, const int* in_sizes, int n_in,
                              void* d_out, int out_size)
{
    const float* hidden = (const float*)d_in[0];
    const float* enc    = (const float*)d_in[1];
    const int*   mask   = (const int*)d_in[2];
    const int fb = (in_sizes[3] == 2) ? 4 : 3;
    const float* cosI = (const float*)d_in[fb + 0];
    const float* sinI = (const float*)d_in[fb + 1];
    const float* cosT = (const float*)d_in[fb + 2];
    const float* sinT = (const float*)d_in[fb + 3];
    const float* W[8]  = { (const float*)d_in[8],  (const float*)d_in[10],
                           (const float*)d_in[12], (const float*)d_in[14],
                           (const float*)d_in[16], (const float*)d_in[18],
                           (const float*)d_in[20], (const float*)d_in[22] };
    const float* bq     = (const float*)d_in[9];
    const float* bk     = (const float*)d_in[11];
    const float* bv     = (const float*)d_in[13];
    const float* bq_add = (const float*)d_in[15];
    const float* bk_add = (const float*)d_in[17];
    const float* bv_add = (const float*)d_in[19];
    const float* bo     = (const float*)d_in[21];
    const float* bo_add = (const float*)d_in[23];
    const float* gq     = (const float*)d_in[24];
    const float* gk     = (const float*)d_in[25];
    const float* gq_add = (const float*)d_in[26];
    const float* gk_add = (const float*)d_in[27];

    float* out = (float*)d_out;

    float *Qp, *Kp, *Vp;
    cudaGetSymbolAddress((void**)&Qp, g_Q);
    cudaGetSymbolAddress((void**)&Kp, g_K);
    cudaGetSymbolAddress((void**)&Vp, g_V);
    __nv_bfloat16 *Whi, *Wlo, *Hhi, *Hlo, *Ehi, *Elo, *Shi, *Slo;
    __nv_bfloat16 *Qhp, *Qlp, *Khp, *Klp, *Vhp, *Vlp;
    cudaGetSymbolAddress((void**)&Whi, g_Whi);
    cudaGetSymbolAddress((void**)&Wlo, g_Wlo);
    cudaGetSymbolAddress((void**)&Hhi, g_Hhi);
    cudaGetSymbolAddress((void**)&Hlo, g_Hlo);
    cudaGetSymbolAddress((void**)&Ehi, g_Ehi);
    cudaGetSymbolAddress((void**)&Elo, g_Elo);
    cudaGetSymbolAddress((void**)&Shi, g_Shi);
    cudaGetSymbolAddress((void**)&Slo, g_Slo);
    cudaGetSymbolAddress((void**)&Qhp, g_Qh);
    cudaGetSymbolAddress((void**)&Qlp, g_Ql);
    cudaGetSymbolAddress((void**)&Khp, g_Kh);
    cudaGetSymbolAddress((void**)&Klp, g_Kl);
    cudaGetSymbolAddress((void**)&Vhp, g_Vh);
    cudaGetSymbolAddress((void**)&Vlp, g_Vl);

    cudaFuncSetAttribute(gemm_mma, cudaFuncAttributeMaxDynamicSharedMemorySize, GEMM_SMEM);
    cudaFuncSetAttribute(attn_mma, cudaFuncAttributeMaxDynamicSharedMemorySize, ATT_SMEM);

    // 1) weight transpose+split, activation split
    dim3 wgrid(DD / 32, DD / 32);
    for (int i = 0; i < 8; i++)
        wsplit_kernel<<<wgrid, dim3(32, 8)>>>(W[i], Whi + (size_t)i * DD * DD,
                                              Wlo + (size_t)i * DD * DD);
    asplit_kernel<<<(M_IMG * DD / 4 + 255) / 256, 256>>>(hidden, Hhi, Hlo, M_IMG * DD / 4);
    asplit_kernel<<<(M_TXT * DD / 4 + 255) / 256, 256>>>(enc, Ehi, Elo, M_TXT * DD / 4);

    // 2) QKV projections (HMMA), scatter into [B,H,S,DH] fp32
    dim3 gi(DD / 128, M_IMG / 128), gt(DD / 128, M_TXT / 128);
    const size_t WN = (size_t)DD * DD;
    gemm_mma<<<gi, 256, GEMM_SMEM>>>(Hhi, Hlo, Whi + 0 * WN, Wlo + 0 * WN, bq, Qp, 0, S_IMG, 0, 1, 0);
    gemm_mma<<<gi, 256, GEMM_SMEM>>>(Hhi, Hlo, Whi + 1 * WN, Wlo + 1 * WN, bk, Kp, 0, S_IMG, 0, 1, 0);
    gemm_mma<<<gi, 256, GEMM_SMEM>>>(Hhi, Hlo, Whi + 2 * WN, Wlo + 2 * WN, bv, Vp, 0, S_IMG, 0, 1, 0);
    gemm_mma<<<gt, 256, GEMM_SMEM>>>(Ehi, Elo, Whi + 3 * WN, Wlo + 3 * WN, bq_add, Qp, 0, S_TXT, 0, 1, S_IMG);
    gemm_mma<<<gt, 256, GEMM_SMEM>>>(Ehi, Elo, Whi + 4 * WN, Wlo + 4 * WN, bk_add, Kp, 0, S_TXT, 0, 1, S_IMG);
    gemm_mma<<<gt, 256, GEMM_SMEM>>>(Ehi, Elo, Whi + 5 * WN, Wlo + 5 * WN, bv_add, Vp, 0, S_TXT, 0, 1, S_IMG);

    // 3) RMSNorm + RoPE + split (Q,K); plain split (V)
    int nrows = BB * NH * S_TOT;
    norm_rope_split<<<nrows, 128>>>(Qp, Qhp, Qlp, gq, gq_add, cosI, sinI, cosT, sinT);
    norm_rope_split<<<nrows, 128>>>(Kp, Khp, Klp, gk, gk_add, cosI, sinI, cosT, sinT);
    asplit_kernel<<<(nrows * DHD / 4 + 255) / 256, 256>>>(Vp, Vhp, Vlp, nrows * DHD / 4);

    // 4) HMMA attention -> Shi/Slo [B,S,D]
    attn_mma<<<dim3(S_TOT / 128, BB * NH), 256, ATT_SMEM>>>(
        Qhp, Qlp, Khp, Klp, Vhp, Vlp, mask, Shi, Slo);

    // 5) output projections (HMMA, gather)
    gemm_mma<<<gi, 256, GEMM_SMEM>>>(Shi, Slo, Whi + 6 * WN, Wlo + 6 * WN, bo, out, 1, S_IMG, 0, 0, 0);
    gemm_mma<<<gt, 256, GEMM_SMEM>>>(Shi, Slo, Whi + 7 * WN, Wlo + 7 * WN, bo_add,
                                     out + IMG_OUT_ELEMS, 1, S_TXT, S_IMG, 0, 0);
}

// round 8
// speedup vs baseline: 3.4367x; 1.1649x over previous
#include <cuda_runtime.h>
#include <cuda_bf16.h>
#include <math.h>
#include <stdint.h>

// ---------------- problem constants ----------------
#define BB     2
#define S_IMG  2048
#define S_TXT  256
#define S_TOT  2304
#define NH     24
#define DHD    128
#define DD     3072
#define ATT_SCALE 0.08838834764831845f
#define RMS_EPS   1e-5f

#define M_IMG  (BB * S_IMG)          // 4096
#define M_TXT  (BB * S_TXT)          // 512
#define M_O    (BB * S_TOT)          // 4608
#define IMG_OUT_ELEMS (M_IMG * DD)

// ---------------- device scratch ----------------
__device__ __nv_bfloat16 g_Qh[BB * NH * S_TOT * DHD], g_Ql[BB * NH * S_TOT * DHD];
__device__ __nv_bfloat16 g_Kh[BB * NH * S_TOT * DHD], g_Kl[BB * NH * S_TOT * DHD];
__device__ __nv_bfloat16 g_Vh[BB * NH * S_TOT * DHD], g_Vl[BB * NH * S_TOT * DHD];

__device__ __nv_bfloat16 g_Whi[8][DD * DD];   // transposed [N,K] bf16 hi
__device__ __nv_bfloat16 g_Wlo[8][DD * DD];   // transposed [N,K] bf16 lo
__device__ __nv_bfloat16 g_Hhi[M_IMG * DD], g_Hlo[M_IMG * DD];
__device__ __nv_bfloat16 g_Ehi[M_TXT * DD], g_Elo[M_TXT * DD];
__device__ __nv_bfloat16 g_Shi[M_O * DD],  g_Slo[M_O * DD];   // attn-out split [B,S,D]

// ---------------- PTX helpers ----------------
__device__ __forceinline__ uint32_t smem_u32(const void* p) {
    uint32_t a;
    asm("{ .reg .u64 t; cvta.to.shared.u64 t, %1; cvt.u32.u64 %0, t; }" : "=r"(a) : "l"(p));
    return a;
}
#define CP_ASYNC16(sa, gp) \
    asm volatile("cp.async.cg.shared.global [%0], [%1], 16;" :: "r"(sa), "l"(gp) : "memory")
#define CP_COMMIT() asm volatile("cp.async.commit_group;" ::: "memory")
#define CP_WAIT(n)  asm volatile("cp.async.wait_group %0;" :: "n"(n) : "memory")

__device__ __forceinline__ void ldsm_x4(uint32_t& r0, uint32_t& r1, uint32_t& r2,
                                        uint32_t& r3, uint32_t addr) {
    asm volatile("ldmatrix.sync.aligned.m8n8.x4.shared.b16 {%0,%1,%2,%3}, [%4];"
                 : "=r"(r0), "=r"(r1), "=r"(r2), "=r"(r3) : "r"(addr));
}
__device__ __forceinline__ void ldsm_x4_t(uint32_t& r0, uint32_t& r1, uint32_t& r2,
                                          uint32_t& r3, uint32_t addr) {
    asm volatile("ldmatrix.sync.aligned.m8n8.x4.trans.shared.b16 {%0,%1,%2,%3}, [%4];"
                 : "=r"(r0), "=r"(r1), "=r"(r2), "=r"(r3) : "r"(addr));
}
__device__ __forceinline__ void mma16816(float* c, const uint32_t* a, const uint32_t* b) {
    asm volatile(
        "mma.sync.aligned.m16n8k16.row.col.f32.bf16.bf16.f32 "
        "{%0,%1,%2,%3}, {%4,%5,%6,%7}, {%8,%9}, {%0,%1,%2,%3};"
        : "+f"(c[0]), "+f"(c[1]), "+f"(c[2]), "+f"(c[3])
        : "r"(a[0]), "r"(a[1]), "r"(a[2]), "r"(a[3]), "r"(b[0]), "r"(b[1]));
}
__device__ __forceinline__ uint32_t pack_bf2(float a, float b) {
    uint32_t r;
    asm("cvt.rn.bf16x2.f32 %0, %1, %2;" : "=r"(r) : "f"(b), "f"(a));
    return r;
}

// ---------------- gemm smem geometry ----------------
#define KC     32
#define NIT    (DD / KC)          // 96
#define ROWB   80
#define TILEB  (128 * ROWB)
#define STAGEB (4 * TILEB)
#define GEMM_SMEM (2 * STAGEB)    // 81920

// ---------------- kernel arg structs ----------------
struct QKVArgs {
    const __nv_bfloat16 *Hhi, *Hlo, *Ehi, *Elo;
    const __nv_bfloat16 *Wh[6], *Wl[6];
    const float *bias[6];
    const float *gq, *gk, *gqa, *gka;
    const float *cosI, *sinI, *cosT, *sinT;
    __nv_bfloat16 *Qh, *Ql, *Kh, *Kl, *Vh, *Vl;
};
struct WOArgs {
    const __nv_bfloat16 *Shi, *Slo;
    const __nv_bfloat16 *WhImg, *WlImg, *WhTxt, *WlTxt;
    const float *bImg, *bTxt;
    float *outImg, *outTxt;
};

// =============================================================================
// Unified QKV projection: grid (24, 36, 3), 256 thr.
//   y<32: img rows (M=4096), y>=32: txt rows (M=512). z: 0=Q 1=K 2=V.
//   Mainloop: bf16x3 HMMA 128x128 tile. Epilogue: bias (+RMSNorm+RoPE for Q/K),
//   bf16 hi/lo split, scatter to [B,H,S,DH].
// =============================================================================
__global__ void __launch_bounds__(256) qkv_mma(QKVArgs P)
{
    extern __shared__ char smraw[];
    const uint32_t sb = smem_u32(smraw);
    const int t = threadIdx.x, lane = t & 31, wid = t >> 5;
    const int warp_m = wid & 1, warp_n = wid >> 1;
    const int z = blockIdx.z;
    const bool img = (blockIdx.y < 32);
    const int bm = (img ? blockIdx.y : (blockIdx.y - 32)) << 7;
    const int bn = blockIdx.x << 7;
    const int wi = img ? z : (z + 3);

    const __nv_bfloat16* Ahi = img ? P.Hhi : P.Ehi;
    const __nv_bfloat16* Alo = img ? P.Hlo : P.Elo;
    const __nv_bfloat16* Bhi = P.Wh[wi];
    const __nv_bfloat16* Blo = P.Wl[wi];
    const float* bias = P.bias[wi];

    // cp.async slots
    const __nv_bfloat16* gsrc[8];
    uint32_t sdst[8];
#pragma unroll
    for (int i = 0; i < 8; i++) {
        int buf = i >> 1;
        int c = t + 256 * (i & 1);
        int row = c >> 2, kc = c & 3;
        const __nv_bfloat16* base = (buf == 0) ? Ahi : (buf == 1) ? Alo
                                  : (buf == 2) ? Bhi : Blo;
        long grow = (buf < 2) ? (long)(bm + row) : (long)(bn + row);
        gsrc[i] = base + (size_t)grow * DD + kc * 8;
        sdst[i] = sb + buf * TILEB + row * ROWB + kc * 16;
    }

    const uint32_t aBase = sb + (warp_m * 64 + (lane & 15)) * ROWB + (lane >> 4) * 16;
    const int brow = (lane & 7) + (((lane >> 4) & 1) << 3);
    const int bkh  = (lane >> 3) & 1;
    const uint32_t bBase = sb + 2 * TILEB + (warp_n * 32 + brow) * ROWB + bkh * 16;

    float acc[4][4][4];
#pragma unroll
    for (int mf = 0; mf < 4; mf++)
#pragma unroll
        for (int nf = 0; nf < 4; nf++)
#pragma unroll
            for (int r = 0; r < 4; r++) acc[mf][nf][r] = 0.f;

    {
#pragma unroll
        for (int i = 0; i < 8; i++) CP_ASYNC16(sdst[i], gsrc[i]);
        CP_COMMIT();
    }

    for (int it = 0; it < NIT; it++) {
        const int s = it & 1;
        if (it + 1 < NIT) {
            const int k0 = (it + 1) * KC;
            const uint32_t so = (s ^ 1) * STAGEB;
#pragma unroll
            for (int i = 0; i < 8; i++) CP_ASYNC16(sdst[i] + so, gsrc[i] + k0);
            CP_COMMIT();
            CP_WAIT(1);
        } else {
            CP_WAIT(0);
        }
        __syncthreads();

        const uint32_t sbase = s * STAGEB;
#pragma unroll
        for (int ks = 0; ks < 2; ks++) {
            uint32_t ah[4][4], al[4][4];
#pragma unroll
            for (int mf = 0; mf < 4; mf++) {
                uint32_t ad = aBase + sbase + mf * (16 * ROWB) + ks * 32;
                ldsm_x4(ah[mf][0], ah[mf][1], ah[mf][2], ah[mf][3], ad);
                ldsm_x4(al[mf][0], al[mf][1], al[mf][2], al[mf][3], ad + TILEB);
            }
            uint32_t bh[4][2], bl2[4][2];
#pragma unroll
            for (int nf2 = 0; nf2 < 2; nf2++) {
                uint32_t bd = bBase + sbase + nf2 * (16 * ROWB) + ks * 32;
                ldsm_x4(bh[2*nf2][0], bh[2*nf2][1], bh[2*nf2+1][0], bh[2*nf2+1][1], bd);
                ldsm_x4(bl2[2*nf2][0], bl2[2*nf2][1], bl2[2*nf2+1][0], bl2[2*nf2+1][1], bd + TILEB);
            }
#pragma unroll
            for (int mf = 0; mf < 4; mf++)
#pragma unroll
                for (int nf = 0; nf < 4; nf++) {
                    mma16816(acc[mf][nf], ah[mf], bh[nf]);
                    mma16816(acc[mf][nf], ah[mf], bl2[nf]);
                    mma16816(acc[mf][nf], al[mf], bh[nf]);
                }
        }
        __syncthreads();
    }

    // ---------------- epilogue ----------------
    const int rgrp = lane >> 2, qlane = lane & 3;
    const int h = blockIdx.x;                 // head (N tile == one head)
    const int seg = img ? S_IMG : S_TXT;
    const int sofs = img ? 0 : S_IMG;
    __nv_bfloat16* Xh = (z == 0) ? P.Qh : (z == 1) ? P.Kh : P.Vh;
    __nv_bfloat16* Xl = (z == 0) ? P.Ql : (z == 1) ? P.Kl : P.Vl;

    // add bias in-place
#pragma unroll
    for (int mf = 0; mf < 4; mf++)
#pragma unroll
        for (int nf = 0; nf < 4; nf++) {
            int colg = bn + warp_n * 32 + nf * 8 + qlane * 2;
            float2 bv = *(const float2*)(bias + colg);
            acc[mf][nf][0] += bv.x; acc[mf][nf][1] += bv.y;
            acc[mf][nf][2] += bv.x; acc[mf][nf][3] += bv.y;
        }

    float rns[4][2];
    if (z < 2) {
        // cross-warp row sum-of-squares (128 rows x 4 warp_n partials)
        float* ssum = (float*)smraw;
#pragma unroll
        for (int mf = 0; mf < 4; mf++)
#pragma unroll
            for (int half = 0; half < 2; half++) {
                float ss = 0.f;
#pragma unroll
                for (int nf = 0; nf < 4; nf++) {
                    float x0 = acc[mf][nf][half * 2 + 0];
                    float x1 = acc[mf][nf][half * 2 + 1];
                    ss += x0 * x0 + x1 * x1;
                }
                ss += __shfl_xor_sync(0xffffffffu, ss, 1);
                ss += __shfl_xor_sync(0xffffffffu, ss, 2);
                if (qlane == 0)
                    ssum[(warp_m * 64 + mf * 16 + half * 8 + rgrp) * 4 + warp_n] = ss;
            }
        __syncthreads();
#pragma unroll
        for (int mf = 0; mf < 4; mf++)
#pragma unroll
            for (int half = 0; half < 2; half++) {
                int lrow = warp_m * 64 + mf * 16 + half * 8 + rgrp;
                float tot = ssum[lrow * 4 + 0] + ssum[lrow * 4 + 1] +
                            ssum[lrow * 4 + 2] + ssum[lrow * 4 + 3];
                rns[mf][half] = rsqrtf(tot * (1.f / DHD) + RMS_EPS);
            }
    }

    const float* g = (z == 0) ? (img ? P.gq : P.gqa)
                   : (z == 1) ? (img ? P.gk : P.gka) : (const float*)0;
    const float* cosT2 = img ? P.cosI : P.cosT;
    const float* sinT2 = img ? P.sinI : P.sinT;

#pragma unroll
    for (int mf = 0; mf < 4; mf++)
#pragma unroll
        for (int half = 0; half < 2; half++) {
            int lrow = warp_m * 64 + mf * 16 + half * 8 + rgrp;
            int m = bm + lrow;
            int b = m / seg, sl = m % seg;
            int sq = sofs + sl;
            size_t obase = (((size_t)(b * NH + h)) * S_TOT + sq) * DHD;
#pragma unroll
            for (int nf = 0; nf < 4; nf++) {
                int colh = warp_n * 32 + nf * 8 + qlane * 2;
                float x0 = acc[mf][nf][half * 2 + 0];
                float x1 = acc[mf][nf][half * 2 + 1];
                if (z < 2) {
                    float rn = rns[mf][half];
                    x0 *= rn * g[colh];
                    x1 *= rn * g[colh + 1];
                    int fi = colh >> 1;
                    float c = cosT2[sl * (DHD / 2) + fi];
                    float sv = sinT2[sl * (DHD / 2) + fi];
                    float o0 = x0 * c - x1 * sv;
                    float o1 = x0 * sv + x1 * c;
                    x0 = o0; x1 = o1;
                }
                uint32_t hp = pack_bf2(x0, x1);
                *(uint32_t*)((char*)Xh + (obase + colh) * 2) = hp;
                float ha = __uint_as_float((hp & 0xffffu) << 16);
                float hb = __uint_as_float(hp & 0xffff0000u);
                *(uint32_t*)((char*)Xl + (obase + colh) * 2) = pack_bf2(x0 - ha, x1 - hb);
            }
        }
}

// =============================================================================
// Unified output projection: grid (24, 36), 256 thr.
//   y<32: img rows -> outImg; y>=32: txt rows -> outTxt. A gathered from [B,S,D].
// =============================================================================
__global__ void __launch_bounds__(256) wo_mma(WOArgs P)
{
    extern __shared__ char smraw[];
    const uint32_t sb = smem_u32(smraw);
    const int t = threadIdx.x, lane = t & 31, wid = t >> 5;
    const int warp_m = wid & 1, warp_n = wid >> 1;
    const bool img = (blockIdx.y < 32);
    const int bm = (img ? blockIdx.y : (blockIdx.y - 32)) << 7;
    const int bn = blockIdx.x << 7;

    const __nv_bfloat16* Bhi = img ? P.WhImg : P.WhTxt;
    const __nv_bfloat16* Blo = img ? P.WlImg : P.WlTxt;
    const float* bias = img ? P.bImg : P.bTxt;
    float* out = img ? P.outImg : P.outTxt;
    const int seg = img ? S_IMG : S_TXT;
    const int sofs = img ? 0 : S_IMG;

    const __nv_bfloat16* gsrc[8];
    uint32_t sdst[8];
#pragma unroll
    for (int i = 0; i < 8; i++) {
        int buf = i >> 1;
        int c = t + 256 * (i & 1);
        int row = c >> 2, kc = c & 3;
        const __nv_bfloat16* base = (buf == 0) ? P.Shi : (buf == 1) ? P.Slo
                                  : (buf == 2) ? Bhi : Blo;
        long grow;
        if (buf < 2) {
            int m = bm + row;
            grow = (long)(m / seg) * S_TOT + sofs + (m % seg);
        } else {
            grow = bn + row;
        }
        gsrc[i] = base + (size_t)grow * DD + kc * 8;
        sdst[i] = sb + buf * TILEB + row * ROWB + kc * 16;
    }

    const uint32_t aBase = sb + (warp_m * 64 + (lane & 15)) * ROWB + (lane >> 4) * 16;
    const int brow = (lane & 7) + (((lane >> 4) & 1) << 3);
    const int bkh  = (lane >> 3) & 1;
    const uint32_t bBase = sb + 2 * TILEB + (warp_n * 32 + brow) * ROWB + bkh * 16;

    float acc[4][4][4];
#pragma unroll
    for (int mf = 0; mf < 4; mf++)
#pragma unroll
        for (int nf = 0; nf < 4; nf++)
#pragma unroll
            for (int r = 0; r < 4; r++) acc[mf][nf][r] = 0.f;

    {
#pragma unroll
        for (int i = 0; i < 8; i++) CP_ASYNC16(sdst[i], gsrc[i]);
        CP_COMMIT();
    }

    for (int it = 0; it < NIT; it++) {
        const int s = it & 1;
        if (it + 1 < NIT) {
            const int k0 = (it + 1) * KC;
            const uint32_t so = (s ^ 1) * STAGEB;
#pragma unroll
            for (int i = 0; i < 8; i++) CP_ASYNC16(sdst[i] + so, gsrc[i] + k0);
            CP_COMMIT();
            CP_WAIT(1);
        } else {
            CP_WAIT(0);
        }
        __syncthreads();

        const uint32_t sbase = s * STAGEB;
#pragma unroll
        for (int ks = 0; ks < 2; ks++) {
            uint32_t ah[4][4], al[4][4];
#pragma unroll
            for (int mf = 0; mf < 4; mf++) {
                uint32_t ad = aBase + sbase + mf * (16 * ROWB) + ks * 32;
                ldsm_x4(ah[mf][0], ah[mf][1], ah[mf][2], ah[mf][3], ad);
                ldsm_x4(al[mf][0], al[mf][1], al[mf][2], al[mf][3], ad + TILEB);
            }
            uint32_t bh[4][2], bl2[4][2];
#pragma unroll
            for (int nf2 = 0; nf2 < 2; nf2++) {
                uint32_t bd = bBase + sbase + nf2 * (16 * ROWB) + ks * 32;
                ldsm_x4(bh[2*nf2][0], bh[2*nf2][1], bh[2*nf2+1][0], bh[2*nf2+1][1], bd);
                ldsm_x4(bl2[2*nf2][0], bl2[2*nf2][1], bl2[2*nf2+1][0], bl2[2*nf2+1][1], bd + TILEB);
            }
#pragma unroll
            for (int mf = 0; mf < 4; mf++)
#pragma unroll
                for (int nf = 0; nf < 4; nf++) {
                    mma16816(acc[mf][nf], ah[mf], bh[nf]);
                    mma16816(acc[mf][nf], ah[mf], bl2[nf]);
                    mma16816(acc[mf][nf], al[mf], bh[nf]);
                }
        }
        __syncthreads();
    }

#pragma unroll
    for (int mf = 0; mf < 4; mf++) {
        const int rbase = bm + warp_m * 64 + mf * 16 + (lane >> 2);
#pragma unroll
        for (int half = 0; half < 2; half++) {
            const int mrow = rbase + half * 8;
            float* orow = out + (size_t)mrow * DD;
#pragma unroll
            for (int nf = 0; nf < 4; nf++) {
                const int col = bn + warp_n * 32 + nf * 8 + (lane & 3) * 2;
                float2 bv = *(const float2*)(bias + col);
                float2 v;
                v.x = acc[mf][nf][half * 2 + 0] + bv.x;
                v.y = acc[mf][nf][half * 2 + 1] + bv.y;
                *(float2*)(orow + col) = v;
            }
        }
    }
}

// =============================================================================
// weight transpose + bf16 split
// =============================================================================
__global__ void __launch_bounds__(256) wsplit_kernel(
    const float* __restrict__ W, __nv_bfloat16* __restrict__ Thi,
    __nv_bfloat16* __restrict__ Tlo)
{
    __shared__ float ts[32][33];
    const int tx = threadIdx.x, ty = threadIdx.y;
    const int n0 = blockIdx.x << 5, k0 = blockIdx.y << 5;
#pragma unroll
    for (int i = 0; i < 4; i++)
        ts[ty + 8 * i][tx] = W[(size_t)(k0 + ty + 8 * i) * DD + n0 + tx];
    __syncthreads();
#pragma unroll
    for (int i = 0; i < 4; i++) {
        float v = ts[tx][ty + 8 * i];
        __nv_bfloat16 h = __float2bfloat16(v);
        float lo = v - __bfloat162float(h);
        size_t o = (size_t)(n0 + ty + 8 * i) * DD + k0 + tx;
        Thi[o] = h;
        Tlo[o] = __float2bfloat16(lo);
    }
}

// =============================================================================
// elementwise bf16 split
// =============================================================================
__global__ void __launch_bounds__(256) asplit_kernel(
    const float* __restrict__ X, __nv_bfloat16* __restrict__ hi,
    __nv_bfloat16* __restrict__ lo, int n4)
{
    int i = blockIdx.x * 256 + threadIdx.x;
    if (i >= n4) return;
    float4 v = ((const float4*)X)[i];
    __nv_bfloat16 h0 = __float2bfloat16(v.x), h1 = __float2bfloat16(v.y);
    __nv_bfloat16 h2 = __float2bfloat16(v.z), h3 = __float2bfloat16(v.w);
    __nv_bfloat162* hp = (__nv_bfloat162*)hi;
    __nv_bfloat162* lp = (__nv_bfloat162*)lo;
    hp[2 * i + 0] = __nv_bfloat162(h0, h1);
    hp[2 * i + 1] = __nv_bfloat162(h2, h3);
    lp[2 * i + 0] = __nv_bfloat162(__float2bfloat16(v.x - __bfloat162float(h0)),
                                   __float2bfloat16(v.y - __bfloat162float(h1)));
    lp[2 * i + 1] = __nv_bfloat162(__float2bfloat16(v.z - __bfloat162float(h2)),
                                   __float2bfloat16(v.w - __bfloat162float(h3)));
}

// =============================================================================
// HMMA flash attention (unchanged from R7, known-good)
// =============================================================================
#define SPB   272
#define ATSB  (64 * SPB)
#define AQB   (128 * SPB)
#define SM_QH 0
#define SM_QL AQB
#define SM_ST0 (2 * AQB)
#define SM_STSZ (4 * ATSB)
#define SM_BIAS (SM_ST0 + 2 * SM_STSZ)
#define ATT_SMEM (SM_BIAS + S_TXT * 4)
#define NKT (S_TOT / 64)

__global__ void __launch_bounds__(256, 1) attn_mma(
    const __nv_bfloat16* __restrict__ Qh, const __nv_bfloat16* __restrict__ Ql,
    const __nv_bfloat16* __restrict__ Kh, const __nv_bfloat16* __restrict__ Kl,
    const __nv_bfloat16* __restrict__ Vh, const __nv_bfloat16* __restrict__ Vl,
    const int* __restrict__ mask,
    __nv_bfloat16* __restrict__ Ohi, __nv_bfloat16* __restrict__ Olo)
{
    extern __shared__ char smraw[];
    const uint32_t sb = smem_u32(smraw);
    const int t = threadIdx.x, lane = t & 31, w = t >> 5;
    const int bh = blockIdx.y, b = bh / NH, h = bh % NH;
    const int q0 = blockIdx.x * 128;
    const size_t bhoff = (size_t)bh * S_TOT * DHD;

    if (t < S_TXT)
        *(float*)(smraw + SM_BIAS + t * 4) = (mask[b * S_TXT + t] == 0) ? -1e9f : 0.f;

    const __nv_bfloat16* kvsrc[4] = { Kh + bhoff, Kl + bhoff, Vh + bhoff, Vl + bhoff };
    auto issue = [&](int kt, int s) {
        const uint32_t stb = sb + SM_ST0 + s * SM_STSZ;
        const int k0 = kt * 64;
#pragma unroll
        for (int c = 0; c < 16; c++) {
            int buf = c >> 2;
            int idx = t + 256 * (c & 3);
            int row = idx >> 4, ch = idx & 15;
            const __nv_bfloat16* gp = kvsrc[buf] + (size_t)(k0 + row) * DHD + ch * 8;
            uint32_t sa = stb + buf * ATSB + row * SPB + ch * 16;
            CP_ASYNC16(sa, gp);
        }
    };

    issue(0, 0);
    CP_COMMIT();

    {
        const __nv_bfloat16* qsrc[2] = { Qh + bhoff + (size_t)q0 * DHD,
                                         Ql + bhoff + (size_t)q0 * DHD };
#pragma unroll
        for (int i = 0; i < 16; i++) {
            int idx = t + 256 * i;
            int buf = idx >> 11, rem = idx & 2047;
            int row = rem >> 4, ch = rem & 15;
            uint4 v = *(const uint4*)(qsrc[buf] + (size_t)row * DHD + ch * 8);
            *(uint4*)(smraw + buf * AQB + row * SPB + ch * 16) = v;
        }
    }

    const uint32_t qA = sb + SM_QH + (w * 16 + (lane & 15)) * SPB + (lane >> 4) * 16;
    const uint32_t kBrel = ((lane >> 4) * 8 + (lane & 7)) * SPB + ((lane >> 3) & 1) * 16;
    const uint32_t vBrel = (lane & 15) * SPB + (lane >> 4) * 16;

    float m0 = -1e30f, m1 = -1e30f, l0 = 0.f, l1 = 0.f;
    float o[16][4];
#pragma unroll
    for (int nf = 0; nf < 16; nf++)
#pragma unroll
        for (int e = 0; e < 4; e++) o[nf][e] = 0.f;

    for (int kt = 0; kt < NKT; kt++) {
        const int s = kt & 1;
        if (kt + 1 < NKT) { issue(kt + 1, s ^ 1); CP_COMMIT(); CP_WAIT(1); }
        else             { CP_WAIT(0); }
        __syncthreads();

        const uint32_t stb = sb + SM_ST0 + s * SM_STSZ;

        float sc[8][4];
#pragma unroll
        for (int j = 0; j < 8; j++)
#pragma unroll
            for (int e = 0; e < 4; e++) sc[j][e] = 0.f;

#pragma unroll
        for (int ks = 0; ks < 8; ks++) {
            uint32_t qh[4], ql[4];
            ldsm_x4(qh[0], qh[1], qh[2], qh[3], qA + ks * 32);
            ldsm_x4(ql[0], ql[1], ql[2], ql[3], qA + AQB + ks * 32);
#pragma unroll
            for (int j2 = 0; j2 < 4; j2++) {
                uint32_t kb[4], klr[4];
                uint32_t kd = stb + kBrel + j2 * (16 * SPB) + ks * 32;
                ldsm_x4(kb[0], kb[1], kb[2], kb[3], kd);
                ldsm_x4(klr[0], klr[1], klr[2], klr[3], kd + ATSB);
                mma16816(sc[2 * j2 + 0], qh, kb);
                mma16816(sc[2 * j2 + 1], qh, kb + 2);
                mma16816(sc[2 * j2 + 0], qh, klr);
                mma16816(sc[2 * j2 + 1], qh, klr + 2);
                mma16816(sc[2 * j2 + 0], ql, kb);
                mma16816(sc[2 * j2 + 1], ql, kb + 2);
            }
        }

        const bool txt_tile = (kt * 64 + 63 >= S_IMG);
#pragma unroll
        for (int j = 0; j < 8; j++) {
            int colb = kt * 64 + j * 8 + (lane & 3) * 2;
            float b0v = 0.f, b1v = 0.f;
            if (txt_tile) {
                if (colb + 0 >= S_IMG) b0v = *(float*)(smraw + SM_BIAS + (colb + 0 - S_IMG) * 4);
                if (colb + 1 >= S_IMG) b1v = *(float*)(smraw + SM_BIAS + (colb + 1 - S_IMG) * 4);
            }
            sc[j][0] = sc[j][0] * ATT_SCALE + b0v;
            sc[j][1] = sc[j][1] * ATT_SCALE + b1v;
            sc[j][2] = sc[j][2] * ATT_SCALE + b0v;
            sc[j][3] = sc[j][3] * ATT_SCALE + b1v;
        }

        float mx0 = -1e30f, mx1 = -1e30f;
#pragma unroll
        for (int j = 0; j < 8; j++) {
            mx0 = fmaxf(mx0, fmaxf(sc[j][0], sc[j][1]));
            mx1 = fmaxf(mx1, fmaxf(sc[j][2], sc[j][3]));
        }
        mx0 = fmaxf(mx0, __shfl_xor_sync(0xffffffffu, mx0, 1));
        mx0 = fmaxf(mx0, __shfl_xor_sync(0xffffffffu, mx0, 2));
        mx1 = fmaxf(mx1, __shfl_xor_sync(0xffffffffu, mx1, 1));
        mx1 = fmaxf(mx1, __shfl_xor_sync(0xffffffffu, mx1, 2));
        float mn0 = fmaxf(m0, mx0), mn1 = fmaxf(m1, mx1);
        float al0 = __expf(m0 - mn0), al1 = __expf(m1 - mn1);
        float rs0 = 0.f, rs1 = 0.f;
#pragma unroll
        for (int j = 0; j < 8; j++) {
            sc[j][0] = __expf(sc[j][0] - mn0); rs0 += sc[j][0];
            sc[j][1] = __expf(sc[j][1] - mn0); rs0 += sc[j][1];
            sc[j][2] = __expf(sc[j][2] - mn1); rs1 += sc[j][2];
            sc[j][3] = __expf(sc[j][3] - mn1); rs1 += sc[j][3];
        }
        rs0 += __shfl_xor_sync(0xffffffffu, rs0, 1);
        rs0 += __shfl_xor_sync(0xffffffffu, rs0, 2);
        rs1 += __shfl_xor_sync(0xffffffffu, rs1, 1);
        rs1 += __shfl_xor_sync(0xffffffffu, rs1, 2);
        l0 = l0 * al0 + rs0; m0 = mn0;
        l1 = l1 * al1 + rs1; m1 = mn1;
#pragma unroll
        for (int nf = 0; nf < 16; nf++) {
            o[nf][0] *= al0; o[nf][1] *= al0;
            o[nf][2] *= al1; o[nf][3] *= al1;
        }

        const uint32_t vtb = stb + 2 * ATSB;
#pragma unroll
        for (int ksv = 0; ksv < 4; ksv++) {
            uint32_t ah[4], alr[4];
#pragma unroll
            for (int q = 0; q < 4; q++) {
                int j = 2 * ksv + (q >> 1);
                float pa = sc[j][(q & 1) * 2 + 0];
                float pb = sc[j][(q & 1) * 2 + 1];
                uint32_t hp = pack_bf2(pa, pb);
                ah[q] = hp;
                float ha = __uint_as_float((hp & 0xffffu) << 16);
                float hb2 = __uint_as_float(hp & 0xffff0000u);
                alr[q] = pack_bf2(pa - ha, pb - hb2);
            }
#pragma unroll
            for (int ch = 0; ch < 8; ch++) {
                uint32_t vb[4], vlr[4];
                uint32_t vd = vtb + vBrel + ksv * (16 * SPB) + ch * 32;
                ldsm_x4_t(vb[0], vb[1], vb[2], vb[3], vd);
                ldsm_x4_t(vlr[0], vlr[1], vlr[2], vlr[3], vd + ATSB);
                mma16816(o[2 * ch + 0], ah, vb);
                mma16816(o[2 * ch + 1], ah, vb + 2);
                mma16816(o[2 * ch + 0], ah, vlr);
                mma16816(o[2 * ch + 1], ah, vlr + 2);
                mma16816(o[2 * ch + 0], alr, vb);
                mma16816(o[2 * ch + 1], alr, vb + 2);
            }
        }
        __syncthreads();
    }

    float inv0 = 1.f / l0, inv1 = 1.f / l1;
    int r0 = q0 + w * 16 + (lane >> 2), r1 = r0 + 8;
    size_t base0 = ((size_t)(b * S_TOT + r0)) * DD + h * DHD;
    size_t base1 = ((size_t)(b * S_TOT + r1)) * DD + h * DHD;
#pragma unroll
    for (int nf = 0; nf < 16; nf++) {
        int d = nf * 8 + (lane & 3) * 2;
        float v0 = o[nf][0] * inv0, v1 = o[nf][1] * inv0;
        uint32_t hp = pack_bf2(v0, v1);
        *(uint32_t*)((char*)Ohi + (base0 + d) * 2) = hp;
        float ha = __uint_as_float((hp & 0xffffu) << 16);
        float hb2 = __uint_as_float(hp & 0xffff0000u);
        *(uint32_t*)((char*)Olo + (base0 + d) * 2) = pack_bf2(v0 - ha, v1 - hb2);

        float u0 = o[nf][2] * inv1, u1 = o[nf][3] * inv1;
        uint32_t hq = pack_bf2(u0, u1);
        *(uint32_t*)((char*)Ohi + (base1 + d) * 2) = hq;
        float hc = __uint_as_float((hq & 0xffffu) << 16);
        float hd = __uint_as_float(hq & 0xffff0000u);
        *(uint32_t*)((char*)Olo + (base1 + d) * 2) = pack_bf2(u0 - hc, u1 - hd);
    }
}

// =============================================================================
// Launch
// =============================================================================
extern "C" void kernel_launch(void* const* d_in, const int* in_sizes, int n_in,
                              void* d_out, int out_size)
{
    const float* hidden = (const float*)d_in[0];
    const float* enc    = (const float*)d_in[1];
    const int*   mask   = (const int*)d_in[2];
    const int fb = (in_sizes[3] == 2) ? 4 : 3;
    const float* cosI = (const float*)d_in[fb + 0];
    const float* sinI = (const float*)d_in[fb + 1];
    const float* cosT = (const float*)d_in[fb + 2];
    const float* sinT = (const float*)d_in[fb + 3];
    const float* W[8]  = { (const float*)d_in[8],  (const float*)d_in[10],
                           (const float*)d_in[12], (const float*)d_in[14],
                           (const float*)d_in[16], (const float*)d_in[18],
                           (const float*)d_in[20], (const float*)d_in[22] };
    const float* biasIn[8] = { (const float*)d_in[9],  (const float*)d_in[11],
                               (const float*)d_in[13], (const float*)d_in[15],
                               (const float*)d_in[17], (const float*)d_in[19],
                               (const float*)d_in[21], (const float*)d_in[23] };
    const float* gq     = (const float*)d_in[24];
    const float* gk     = (const float*)d_in[25];
    const float* gq_add = (const float*)d_in[26];
    const float* gk_add = (const float*)d_in[27];

    float* out = (float*)d_out;

    __nv_bfloat16 *Whi, *Wlo, *Hhi, *Hlo, *Ehi, *Elo, *Shi, *Slo;
    __nv_bfloat16 *Qhp, *Qlp, *Khp, *Klp, *Vhp, *Vlp;
    cudaGetSymbolAddress((void**)&Whi, g_Whi);
    cudaGetSymbolAddress((void**)&Wlo, g_Wlo);
    cudaGetSymbolAddress((void**)&Hhi, g_Hhi);
    cudaGetSymbolAddress((void**)&Hlo, g_Hlo);
    cudaGetSymbolAddress((void**)&Ehi, g_Ehi);
    cudaGetSymbolAddress((void**)&Elo, g_Elo);
    cudaGetSymbolAddress((void**)&Shi, g_Shi);
    cudaGetSymbolAddress((void**)&Slo, g_Slo);
    cudaGetSymbolAddress((void**)&Qhp, g_Qh);
    cudaGetSymbolAddress((void**)&Qlp, g_Ql);
    cudaGetSymbolAddress((void**)&Khp, g_Kh);
    cudaGetSymbolAddress((void**)&Klp, g_Kl);
    cudaGetSymbolAddress((void**)&Vhp, g_Vh);
    cudaGetSymbolAddress((void**)&Vlp, g_Vl);

    cudaFuncSetAttribute(qkv_mma, cudaFuncAttributeMaxDynamicSharedMemorySize, GEMM_SMEM);
    cudaFuncSetAttribute(wo_mma, cudaFuncAttributeMaxDynamicSharedMemorySize, GEMM_SMEM);
    cudaFuncSetAttribute(attn_mma, cudaFuncAttributeMaxDynamicSharedMemorySize, ATT_SMEM);

    // 1) weight transpose+split, activation split
    dim3 wgrid(DD / 32, DD / 32);
    for (int i = 0; i < 8; i++)
        wsplit_kernel<<<wgrid, dim3(32, 8)>>>(W[i], Whi + (size_t)i * DD * DD,
                                              Wlo + (size_t)i * DD * DD);
    asplit_kernel<<<(M_IMG * DD / 4 + 255) / 256, 256>>>(hidden, Hhi, Hlo, M_IMG * DD / 4);
    asplit_kernel<<<(M_TXT * DD / 4 + 255) / 256, 256>>>(enc, Ehi, Elo, M_TXT * DD / 4);

    // 2) unified QKV projection + fused norm/rope/split
    const size_t WN = (size_t)DD * DD;
    QKVArgs qa;
    qa.Hhi = Hhi; qa.Hlo = Hlo; qa.Ehi = Ehi; qa.Elo = Elo;
    for (int i = 0; i < 6; i++) {
        qa.Wh[i] = Whi + (size_t)i * WN;
        qa.Wl[i] = Wlo + (size_t)i * WN;
        qa.bias[i] = biasIn[i];
    }
    qa.gq = gq; qa.gk = gk; qa.gqa = gq_add; qa.gka = gk_add;
    qa.cosI = cosI; qa.sinI = sinI; qa.cosT = cosT; qa.sinT = sinT;
    qa.Qh = Qhp; qa.Ql = Qlp; qa.Kh = Khp; qa.Kl = Klp; qa.Vh = Vhp; qa.Vl = Vlp;
    qkv_mma<<<dim3(DD / 128, 36, 3), 256, GEMM_SMEM>>>(qa);

    // 3) HMMA attention -> Shi/Slo [B,S,D]
    attn_mma<<<dim3(S_TOT / 128, BB * NH), 256, ATT_SMEM>>>(
        Qhp, Qlp, Khp, Klp, Vhp, Vlp, mask, Shi, Slo);

    // 4) unified output projections
    WOArgs wa;
    wa.Shi = Shi; wa.Slo = Slo;
    wa.WhImg = Whi + 6 * WN; wa.WlImg = Wlo + 6 * WN;
    wa.WhTxt = Whi + 7 * WN; wa.WlTxt = Wlo + 7 * WN;
    wa.bImg = biasIn[6]; wa.bTxt = biasIn[7];
    wa.outImg = out; wa.outTxt = out + IMG_OUT_ELEMS;
    wo_mma<<<dim3(DD / 128, 36), 256, GEMM_SMEM>>>(wa);
}